// round 13
// baseline (speedup 1.0000x reference)
#include <cuda_runtime.h>
#include <cuda_bf16.h>
#include <math.h>
#include <cstdint>

#define NN 4096
#define DD 512
#define HH 8
#define DHH 64
#define MEMM 4
#define WINN 512
#define JJ (NN + MEMM)   /* 4100 */
#define JP 4160          /* padded to multiple of 64 */
#define QK_SCALE 10.0f

// ---------------------------------------------------------------------------
// Warp-MMA helpers (arch-neutral PTX: valid under compute_103)
// ---------------------------------------------------------------------------
__device__ __forceinline__ uint32_t smem_to_u32(const void* smem_ptr) {
    uint32_t addr;
    asm("{ .reg .u64 tmp; cvta.to.shared.u64 tmp, %1; cvt.u32.u64 %0, tmp; }"
        : "=r"(addr) : "l"(smem_ptr));
    return addr;
}
__device__ __forceinline__ void ldsm4(uint32_t& r0, uint32_t& r1, uint32_t& r2, uint32_t& r3,
                                      uint32_t a) {
    asm volatile("ldmatrix.sync.aligned.m8n8.x4.shared.b16 {%0,%1,%2,%3}, [%4];"
                 : "=r"(r0), "=r"(r1), "=r"(r2), "=r"(r3) : "r"(a));
}
__device__ __forceinline__ void ldsm4t(uint32_t& r0, uint32_t& r1, uint32_t& r2, uint32_t& r3,
                                       uint32_t a) {
    asm volatile("ldmatrix.sync.aligned.m8n8.x4.trans.shared.b16 {%0,%1,%2,%3}, [%4];"
                 : "=r"(r0), "=r"(r1), "=r"(r2), "=r"(r3) : "r"(a));
}
__device__ __forceinline__ void mma16816(float* d,
                                         uint32_t a0, uint32_t a1, uint32_t a2, uint32_t a3,
                                         uint32_t b0, uint32_t b1) {
    asm volatile("mma.sync.aligned.m16n8k16.row.col.f32.bf16.bf16.f32 "
                 "{%0,%1,%2,%3}, {%4,%5,%6,%7}, {%8,%9}, {%0,%1,%2,%3};"
                 : "+f"(d[0]), "+f"(d[1]), "+f"(d[2]), "+f"(d[3])
                 : "r"(a0), "r"(a1), "r"(a2), "r"(a3), "r"(b0), "r"(b1));
}
__device__ __forceinline__ uint32_t pack_bf16(float a, float b) {
    __nv_bfloat162 h = __floats2bfloat162_rn(a, b);
    return *(uint32_t*)&h;
}

// ---------------------------------------------------------------------------
// Scratch (device globals)
// ---------------------------------------------------------------------------
__device__ float g_P[NN * 2048];        // fused projection out: [n][Q|K|V|G]
__device__ float g_cos[NN * 64], g_sin[NN * 64];   // rope tables
// bf16 hi/lo splits
__device__ __nv_bfloat16 g_xh[NN * DD],   g_xl[NN * DD];       // x
__device__ __nv_bfloat16 g_Wth[2048 * 512], g_Wtl[2048 * 512]; // [Wq|Wk|Wv|Wg]^T  [n][k]
__device__ __nv_bfloat16 g_Woth[512 * 512], g_Wotl[512 * 512]; // Wo^T [n][k]
__device__ __nv_bfloat16 g_ah[NN * 512],  g_al[NN * 512];      // gated attention out
// attention operands (bf16 hi/lo), zero-padded tails. Q is pre-scaled by QK_SCALE.
__device__ __nv_bfloat16 g_Qh[HH * NN * 64], g_Ql[HH * NN * 64];   // [h][n][d]
__device__ __nv_bfloat16 g_Kh[HH * JP * 64], g_Kl[HH * JP * 64];   // [h][j][d]
__device__ __nv_bfloat16 g_Vh[HH * JP * 64], g_Vl[HH * JP * 64];   // [h][j][d]

// ---------------------------------------------------------------------------
// Merged prologue: conv_split (blocks 0..8191), sincos (8192..9215),
// convert_wt x5 (9216..10495)
// ---------------------------------------------------------------------------
#define PRO_CONV_BLKS  8192
#define PRO_SIN_BLKS   1024
#define PRO_WT_BLKS    1280     /* 5 * 256 */

__global__ void __launch_bounds__(256) prologue(
    const float* __restrict__ x, const float* __restrict__ freqs,
    const float* __restrict__ Wq, const float* __restrict__ Wk,
    const float* __restrict__ Wv, const float* __restrict__ Wg,
    const float* __restrict__ Wo)
{
    const int b = blockIdx.x;
    const int tid = threadIdx.x;
    if (b < PRO_CONV_BLKS) {
        const int i = b * 256 + tid;   // < NN*DD = 2M exactly
        const float v = x[i];
        const __nv_bfloat16 h = __float2bfloat16(v);
        g_xh[i] = h;
        g_xl[i] = __float2bfloat16(v - __bfloat162float(h));
    } else if (b < PRO_CONV_BLKS + PRO_SIN_BLKS) {
        const int i = (b - PRO_CONV_BLKS) * 256 + tid;   // < NN*64 = 256K exactly
        float s, c;
        sincosf(freqs[i], &s, &c);
        g_cos[i] = c;
        g_sin[i] = s;
    } else {
        __shared__ float t[32][33];
        const int bb = b - PRO_CONV_BLKS - PRO_SIN_BLKS;
        const int z = bb >> 8;             // 0..4
        const int tile = bb & 255;
        const float* W = (z == 0) ? Wq : (z == 1) ? Wk : (z == 2) ? Wv : (z == 3) ? Wg : Wo;
        __nv_bfloat16* Dh = (z < 4) ? (g_Wth + (size_t)z * 512 * 512) : g_Woth;
        __nv_bfloat16* Dl = (z < 4) ? (g_Wtl + (size_t)z * 512 * 512) : g_Wotl;
        const int bx = (tile & 15) * 32;   // n
        const int by = (tile >> 4) * 32;   // k
        const int tx = tid & 31, ty = tid >> 5;
#pragma unroll
        for (int i = ty; i < 32; i += 8)
            t[i][tx] = W[(size_t)(by + i) * 512 + bx + tx];
        __syncthreads();
#pragma unroll
        for (int i = ty; i < 32; i += 8) {
            const float v = t[tx][i];
            const __nv_bfloat16 h = __float2bfloat16(v);
            const __nv_bfloat16 l = __float2bfloat16(v - __bfloat162float(h));
            const size_t o = (size_t)(bx + i) * 512 + by + tx;
            Dh[o] = h; Dl[o] = l;
        }
    }
}

// ---------------------------------------------------------------------------
// HMMA split-bf16 GEMM. CTA tile 128(m) x 64(n), warp tile 32x32, 8 warps,
// 3 CTAs/SM. LDG+STS tile fills (unchanged from R10/R12).
// ---------------------------------------------------------------------------
#define SST 72
#define GEMM_SMEM ((2 * 128 + 2 * 64) * SST * 2)   /* 55296 */

__global__ void __launch_bounds__(256, 3) hmma_gemm(
    const __nv_bfloat16* __restrict__ Ah, const __nv_bfloat16* __restrict__ Al,
    const __nv_bfloat16* __restrict__ Bh, const __nv_bfloat16* __restrict__ Bl,
    float* __restrict__ C, int Ntot, int K,
    const float* __restrict__ bias, int bias_off)
{
    extern __shared__ __align__(16) __nv_bfloat16 sm[];
    __nv_bfloat16* sAh = sm;                     // 128 x SST
    __nv_bfloat16* sAl = sm + 128 * SST;         // 128 x SST
    __nv_bfloat16* sBh = sm + 256 * SST;         // 64 x SST
    __nv_bfloat16* sBl = sm + 320 * SST;         // 64 x SST

    const int tid = threadIdx.x;
    const int lane = tid & 31, wid = tid >> 5;
    const int wm = wid & 3, wn = wid >> 2;       // 4 m-warps x 2 n-warps
    const int m0 = blockIdx.y * 128, n0 = blockIdx.x * 64;

    float acc[2][4][4];
#pragma unroll
    for (int i = 0; i < 2; i++)
#pragma unroll
        for (int j = 0; j < 4; j++)
#pragma unroll
            for (int k = 0; k < 4; k++) acc[i][j][k] = 0.0f;

    // loader indices
    const int ar = tid >> 1;               // 0..127
    const int ac = (tid & 1) * 32;         // elems
    const int br = tid >> 2;               // 0..63
    const int bc = (tid & 3) * 16;

    const uint32_t smbase = smem_to_u32(sm);
    const uint32_t afrag = (uint32_t)(((wm * 32 + (lane & 15)) * SST + (lane >> 4) * 8) * 2);
    const uint32_t bfrag = (uint32_t)(((wn * 32 + (lane & 15)) * SST + (lane >> 4) * 8) * 2);
    const uint32_t aAh = smbase + afrag;
    const uint32_t aAl = smbase + 128 * SST * 2 + afrag;
    const uint32_t aBh = smbase + 256 * SST * 2 + bfrag;
    const uint32_t aBl = smbase + 320 * SST * 2 + bfrag;

    for (int kc = 0; kc < K; kc += 64) {
        __syncthreads();
        {
            const size_t ga = (size_t)(m0 + ar) * K + kc + ac;
#pragma unroll
            for (int i = 0; i < 4; i++) {
                *(float4*)&sAh[ar * SST + ac + i * 8] = *(const float4*)&Ah[ga + i * 8];
                *(float4*)&sAl[ar * SST + ac + i * 8] = *(const float4*)&Al[ga + i * 8];
            }
            const size_t gb = (size_t)(n0 + br) * K + kc + bc;
#pragma unroll
            for (int i = 0; i < 2; i++) {
                *(float4*)&sBh[br * SST + bc + i * 8] = *(const float4*)&Bh[gb + i * 8];
                *(float4*)&sBl[br * SST + bc + i * 8] = *(const float4*)&Bl[gb + i * 8];
            }
        }
        __syncthreads();

#pragma unroll
        for (int kk = 0; kk < 4; kk++) {
            const uint32_t ko = kk * 32;
            uint32_t ah[8], al[8], bh[8], bl[8];
            ldsm4(ah[0], ah[1], ah[2], ah[3], aAh + ko);
            ldsm4(ah[4], ah[5], ah[6], ah[7], aAh + ko + 16 * SST * 2);
            ldsm4(al[0], al[1], al[2], al[3], aAl + ko);
            ldsm4(al[4], al[5], al[6], al[7], aAl + ko + 16 * SST * 2);
            ldsm4(bh[0], bh[1], bh[2], bh[3], aBh + ko);
            ldsm4(bh[4], bh[5], bh[6], bh[7], aBh + ko + 16 * SST * 2);
            ldsm4(bl[0], bl[1], bl[2], bl[3], aBl + ko);
            ldsm4(bl[4], bl[5], bl[6], bl[7], aBl + ko + 16 * SST * 2);
#pragma unroll
            for (int bn = 0; bn < 4; bn++) {
                const uint32_t bh0 = bh[(bn >> 1) * 4 + (bn & 1)];
                const uint32_t bh1 = bh[(bn >> 1) * 4 + (bn & 1) + 2];
                const uint32_t bl0 = bl[(bn >> 1) * 4 + (bn & 1)];
                const uint32_t bl1 = bl[(bn >> 1) * 4 + (bn & 1) + 2];
                mma16816(acc[0][bn], ah[0], ah[1], ah[2], ah[3], bh0, bh1);
                mma16816(acc[0][bn], ah[0], ah[1], ah[2], ah[3], bl0, bl1);
                mma16816(acc[0][bn], al[0], al[1], al[2], al[3], bh0, bh1);
                mma16816(acc[1][bn], ah[4], ah[5], ah[6], ah[7], bh0, bh1);
                mma16816(acc[1][bn], ah[4], ah[5], ah[6], ah[7], bl0, bl1);
                mma16816(acc[1][bn], al[4], al[5], al[6], al[7], bh0, bh1);
            }
        }
    }

    const int gid = lane >> 2;
    const int qc = (lane & 3) * 2;
#pragma unroll
    for (int mf = 0; mf < 2; mf++) {
        const int row = m0 + wm * 32 + mf * 16 + gid;
#pragma unroll
        for (int nf = 0; nf < 4; nf++) {
            const int col = n0 + wn * 32 + nf * 8 + qc;
            float2 v0 = make_float2(acc[mf][nf][0], acc[mf][nf][1]);
            float2 v1 = make_float2(acc[mf][nf][2], acc[mf][nf][3]);
            if (bias != nullptr && col >= bias_off) {
                const float b0 = bias[col - bias_off], b1 = bias[col - bias_off + 1];
                v0.x += b0; v0.y += b1;
                v1.x += b0; v1.y += b1;
            }
            *(float2*)&C[(size_t)row * Ntot + col] = v0;
            *(float2*)&C[(size_t)(row + 8) * Ntot + col] = v1;
        }
    }
}

// ---------------------------------------------------------------------------
// prep: per-(h,n) l2norm + RoPE (table-driven), emit bf16 hi/lo Q/K/V.
// Q is pre-scaled by QK_SCALE so attention needs no per-logit scaling.
// ---------------------------------------------------------------------------
__device__ __forceinline__ void split_store(__nv_bfloat16* dh, __nv_bfloat16* dl, float v) {
    __nv_bfloat16 h = __float2bfloat16(v);
    *dh = h;
    *dl = __float2bfloat16(v - __bfloat162float(h));
}

__global__ void __launch_bounds__(256) prep_kernel(
    const float* __restrict__ mem_k, const float* __restrict__ mem_v)
{
    const int warp = (blockIdx.x * blockDim.x + threadIdx.x) >> 5;
    const int lane = threadIdx.x & 31;
    const int total = HH * NN;
    if (warp < total) {
        const int h = warp >> 12;
        const int n = warp & (NN - 1);
        const float c0 = g_cos[n * 64 + lane];
        const float c1 = g_cos[n * 64 + lane + 32];
        const float s0 = g_sin[n * 64 + lane];
        const float s1 = g_sin[n * 64 + lane + 32];
        {
            const float* r = &g_P[n * 2048 + h * 64];
            float t0 = r[lane], t1 = r[lane + 32];
            float ss = t0 * t0 + t1 * t1;
#pragma unroll
            for (int o = 16; o; o >>= 1) ss += __shfl_xor_sync(0xffffffffu, ss, o);
            const float inv = QK_SCALE / fmaxf(sqrtf(ss), 1e-12f);   // scale folded in
            t0 *= inv; t1 *= inv;
            const size_t base = ((size_t)h * NN + n) * 64;
            split_store(&g_Qh[base + lane], &g_Ql[base + lane], t0 * c0 - t1 * s0);
            split_store(&g_Qh[base + lane + 32], &g_Ql[base + lane + 32], t1 * c1 + t0 * s1);
        }
        {
            const float* r = &g_P[n * 2048 + 512 + h * 64];
            float t0 = r[lane], t1 = r[lane + 32];
            float ss = t0 * t0 + t1 * t1;
#pragma unroll
            for (int o = 16; o; o >>= 1) ss += __shfl_xor_sync(0xffffffffu, ss, o);
            const float inv = 1.0f / fmaxf(sqrtf(ss), 1e-12f);
            t0 *= inv; t1 *= inv;
            const size_t base = ((size_t)h * JP + MEMM + n) * 64;
            split_store(&g_Kh[base + lane], &g_Kl[base + lane], t0 * c0 - t1 * s0);
            split_store(&g_Kh[base + lane + 32], &g_Kl[base + lane + 32], t1 * c1 + t0 * s1);
        }
        {
            const float* r = &g_P[n * 2048 + 1024 + h * 64];
            const size_t base = ((size_t)h * JP + MEMM + n) * 64;
            split_store(&g_Vh[base + lane], &g_Vl[base + lane], r[lane]);
            split_store(&g_Vh[base + lane + 32], &g_Vl[base + lane + 32], r[lane + 32]);
        }
    } else if (warp < total + HH * MEMM) {
        const int t = warp - total;
        const int h = t >> 2, m = t & 3;
        const float* r = &mem_k[(h * MEMM + m) * 64];
        float t0 = r[lane], t1 = r[lane + 32];
        float ss = t0 * t0 + t1 * t1;
#pragma unroll
        for (int o = 16; o; o >>= 1) ss += __shfl_xor_sync(0xffffffffu, ss, o);
        const float inv = 1.0f / fmaxf(sqrtf(ss), 1e-12f);
        const size_t kb = ((size_t)h * JP + m) * 64;
        split_store(&g_Kh[kb + lane], &g_Kl[kb + lane], t0 * inv);
        split_store(&g_Kh[kb + lane + 32], &g_Kl[kb + lane + 32], t1 * inv);
        const float* rv = &mem_v[(h * MEMM + m) * 64];
        split_store(&g_Vh[kb + lane], &g_Vl[kb + lane], rv[lane]);
        split_store(&g_Vh[kb + lane + 32], &g_Vl[kb + lane + 32], rv[lane + 32]);
    }
}

// ---------------------------------------------------------------------------
// HMMA banded flash attention, q-tile=64, 4 warps/128 threads, 4 CTAs/SM.
// Same per-warp math as R12; finer CTA granularity for latency hiding.
// ---------------------------------------------------------------------------
#define AST 72

__global__ void __launch_bounds__(128, 4) attn_kernel()
{
    __shared__ __align__(16) __nv_bfloat16 sm4[4][64 * AST];

    const int h = blockIdx.y;
    const int iq0 = blockIdx.x * 64;
    const int tid = threadIdx.x;
    const int lane = tid & 31, w = tid >> 5;   // 4 warps: q rows w*16..w*16+15
    const int gid = lane >> 2;
    const int qc = (lane & 3) * 2;

    const uint32_t sKh = smem_to_u32(sm4[0]);
    const uint32_t sKl = smem_to_u32(sm4[1]);
    const uint32_t sVh = smem_to_u32(sm4[2]);
    const uint32_t sVl = smem_to_u32(sm4[3]);

    // ---- stage Q (64 rows: hi in array 0, lo in array 1), load Q frags once ----
    {
        const int r = tid >> 1, half = (tid & 1) * 32;   // r: 0..63
        const size_t gq = ((size_t)h * NN + iq0 + r) * 64 + half;
        const int so = r * AST + half;
#pragma unroll
        for (int i = 0; i < 4; i++) {
            *(float4*)&sm4[0][so + i * 8] = *(const float4*)&g_Qh[gq + i * 8];
            *(float4*)&sm4[1][so + i * 8] = *(const float4*)&g_Ql[gq + i * 8];
        }
    }
    __syncthreads();
    uint32_t qh[4][4], ql[4][4];
    {
        const int qrow = w * 16 + (lane & 15);           // 0..63
        const uint32_t off = (uint32_t)((qrow * AST + (lane >> 4) * 8) * 2);
#pragma unroll
        for (int ks = 0; ks < 4; ks++) {
            ldsm4(qh[ks][0], qh[ks][1], qh[ks][2], qh[ks][3], sKh + off + ks * 32);
            ldsm4(ql[ks][0], ql[ks][1], ql[ks][2], ql[ks][3], sKl + off + ks * 32);
        }
    }
    __syncthreads();

    float o[8][4];
#pragma unroll
    for (int f = 0; f < 8; f++)
#pragma unroll
        for (int k = 0; k < 4; k++) o[f][k] = 0.0f;
    float m0 = -1e9f, m1 = -1e9f, l0 = 0.0f, l1 = 0.0f;

    const int qpos0 = MEMM + iq0 + w * 16 + gid;
    const int qpos1 = qpos0 + 8;

    int lo = iq0 + MEMM - WINN; if (lo < 0) lo = 0;
    int hi = iq0 + 63 + MEMM + WINN + 1; if (hi > JJ) hi = JJ;

    const uint32_t lmoff = (uint32_t)((((lane & 15)) * AST + (lane >> 4) * 8) * 2);

    for (int j0 = lo & ~63; j0 < hi; j0 += 64) {
        // ---- load K/V tile (hi+lo), 128 threads: thread -> row tid>>1, 32-col half ----
        {
            const int r = tid >> 1;
            const int c = (tid & 1) * 32;
            const size_t gb = ((size_t)h * JP + j0 + r) * 64 + c;
            const int so = r * AST + c;
#pragma unroll
            for (int i = 0; i < 4; i++) {
                *(float4*)&sm4[0][so + i * 8] = *(const float4*)&g_Kh[gb + i * 8];
                *(float4*)&sm4[1][so + i * 8] = *(const float4*)&g_Kl[gb + i * 8];
                *(float4*)&sm4[2][so + i * 8] = *(const float4*)&g_Vh[gb + i * 8];
                *(float4*)&sm4[3][so + i * 8] = *(const float4*)&g_Vl[gb + i * 8];
            }
        }
        __syncthreads();

        float s[8][4];
#pragma unroll
        for (int f = 0; f < 8; f++)
#pragma unroll
            for (int k = 0; k < 4; k++) s[f][k] = 0.0f;

#pragma unroll
        for (int ks = 0; ks < 4; ks++) {
#pragma unroll
            for (int g = 0; g < 4; g++) {
                const uint32_t ba = lmoff + (uint32_t)(g * 16 * AST * 2) + ks * 32;
                uint32_t kh[4], kl[4];
                ldsm4(kh[0], kh[1], kh[2], kh[3], sKh + ba);
                ldsm4(kl[0], kl[1], kl[2], kl[3], sKl + ba);
                mma16816(s[2 * g],     qh[ks][0], qh[ks][1], qh[ks][2], qh[ks][3], kh[0], kh[2]);
                mma16816(s[2 * g + 1], qh[ks][0], qh[ks][1], qh[ks][2], qh[ks][3], kh[1], kh[3]);
                mma16816(s[2 * g],     qh[ks][0], qh[ks][1], qh[ks][2], qh[ks][3], kl[0], kl[2]);
                mma16816(s[2 * g + 1], qh[ks][0], qh[ks][1], qh[ks][2], qh[ks][3], kl[1], kl[3]);
                mma16816(s[2 * g],     ql[ks][0], ql[ks][1], ql[ks][2], ql[ks][3], kh[0], kh[2]);
                mma16816(s[2 * g + 1], ql[ks][0], ql[ks][1], ql[ks][2], ql[ks][3], kh[1], kh[3]);
            }
        }

        // logits are pre-scaled; only masking remains
        const bool needmask = (MEMM + iq0 + 63 - j0 > WINN) ||
                              (j0 + 63 - (MEMM + iq0) > WINN) ||
                              (j0 + 64 > JJ);
        if (needmask) {
#pragma unroll
            for (int f = 0; f < 8; f++) {
                const int k0 = j0 + 8 * f + qc;
                const int k1 = k0 + 1;
                const bool ok00 = (qpos0 - k0 <= WINN) && (k0 - qpos0 <= WINN) && (k0 < JJ);
                const bool ok01 = (qpos0 - k1 <= WINN) && (k1 - qpos0 <= WINN) && (k1 < JJ);
                const bool ok10 = (qpos1 - k0 <= WINN) && (k0 - qpos1 <= WINN) && (k0 < JJ);
                const bool ok11 = (qpos1 - k1 <= WINN) && (k1 - qpos1 <= WINN) && (k1 < JJ);
                if (!ok00) s[f][0] = -1e30f;
                if (!ok01) s[f][1] = -1e30f;
                if (!ok10) s[f][2] = -1e30f;
                if (!ok11) s[f][3] = -1e30f;
            }
        }

        float mx0 = -1e30f, mx1 = -1e30f;
#pragma unroll
        for (int f = 0; f < 8; f++) {
            mx0 = fmaxf(mx0, fmaxf(s[f][0], s[f][1]));
            mx1 = fmaxf(mx1, fmaxf(s[f][2], s[f][3]));
        }
        mx0 = fmaxf(mx0, __shfl_xor_sync(0xffffffffu, mx0, 1));
        mx0 = fmaxf(mx0, __shfl_xor_sync(0xffffffffu, mx0, 2));
        mx1 = fmaxf(mx1, __shfl_xor_sync(0xffffffffu, mx1, 1));
        mx1 = fmaxf(mx1, __shfl_xor_sync(0xffffffffu, mx1, 2));
        const float mn0 = fmaxf(m0, mx0), mn1 = fmaxf(m1, mx1);
        const float corr0 = __expf(m0 - mn0), corr1 = __expf(m1 - mn1);
        m0 = mn0; m1 = mn1;

        float ls0 = 0.0f, ls1 = 0.0f;
#pragma unroll
        for (int f = 0; f < 8; f++) {
            s[f][0] = __expf(s[f][0] - mn0);
            s[f][1] = __expf(s[f][1] - mn0);
            s[f][2] = __expf(s[f][2] - mn1);
            s[f][3] = __expf(s[f][3] - mn1);
            ls0 += s[f][0] + s[f][1];
            ls1 += s[f][2] + s[f][3];
        }
        ls0 += __shfl_xor_sync(0xffffffffu, ls0, 1);
        ls0 += __shfl_xor_sync(0xffffffffu, ls0, 2);
        ls1 += __shfl_xor_sync(0xffffffffu, ls1, 1);
        ls1 += __shfl_xor_sync(0xffffffffu, ls1, 2);
        l0 = l0 * corr0 + ls0;
        l1 = l1 * corr1 + ls1;
#pragma unroll
        for (int f = 0; f < 8; f++) {
            o[f][0] *= corr0; o[f][1] *= corr0;
            o[f][2] *= corr1; o[f][3] *= corr1;
        }

        uint32_t pah[4][4], pal[4][4];
#pragma unroll
        for (int g = 0; g < 4; g++) {
            float p00 = s[2 * g][0],     p01 = s[2 * g][1];
            float p10 = s[2 * g][2],     p11 = s[2 * g][3];
            float p20 = s[2 * g + 1][0], p21 = s[2 * g + 1][1];
            float p30 = s[2 * g + 1][2], p31 = s[2 * g + 1][3];
            float h00 = __bfloat162float(__float2bfloat16(p00));
            float h01 = __bfloat162float(__float2bfloat16(p01));
            float h10 = __bfloat162float(__float2bfloat16(p10));
            float h11 = __bfloat162float(__float2bfloat16(p11));
            float h20 = __bfloat162float(__float2bfloat16(p20));
            float h21 = __bfloat162float(__float2bfloat16(p21));
            float h30 = __bfloat162float(__float2bfloat16(p30));
            float h31 = __bfloat162float(__float2bfloat16(p31));
            pah[g][0] = pack_bf16(h00, h01);
            pah[g][1] = pack_bf16(h10, h11);
            pah[g][2] = pack_bf16(h20, h21);
            pah[g][3] = pack_bf16(h30, h31);
            pal[g][0] = pack_bf16(p00 - h00, p01 - h01);
            pal[g][1] = pack_bf16(p10 - h10, p11 - h11);
            pal[g][2] = pack_bf16(p20 - h20, p21 - h21);
            pal[g][3] = pack_bf16(p30 - h30, p31 - h31);
        }

#pragma unroll
        for (int g = 0; g < 4; g++) {
#pragma unroll
            for (int dg = 0; dg < 4; dg++) {
                const uint32_t ba = lmoff + (uint32_t)(g * 16 * AST * 2) + dg * 32;
                uint32_t vh[4], vl[4];
                ldsm4t(vh[0], vh[1], vh[2], vh[3], sVh + ba);
                ldsm4t(vl[0], vl[1], vl[2], vl[3], sVl + ba);
                mma16816(o[2 * dg],     pah[g][0], pah[g][1], pah[g][2], pah[g][3], vh[0], vh[1]);
                mma16816(o[2 * dg + 1], pah[g][0], pah[g][1], pah[g][2], pah[g][3], vh[2], vh[3]);
                mma16816(o[2 * dg],     pah[g][0], pah[g][1], pah[g][2], pah[g][3], vl[0], vl[1]);
                mma16816(o[2 * dg + 1], pah[g][0], pah[g][1], pah[g][2], pah[g][3], vl[2], vl[3]);
                mma16816(o[2 * dg],     pal[g][0], pal[g][1], pal[g][2], pal[g][3], vh[0], vh[1]);
                mma16816(o[2 * dg + 1], pal[g][0], pal[g][1], pal[g][2], pal[g][3], vh[2], vh[3]);
            }
        }
        __syncthreads();
    }

    // ---- epilogue: normalize, gate (sigmoid), bf16 split, write ----
    const float inv0 = 1.0f / l0, inv1 = 1.0f / l1;
    const int row0 = iq0 + w * 16 + gid;
#pragma unroll
    for (int f = 0; f < 8; f++) {
        const int col = h * 64 + 8 * f + qc;
        const float2 gA = *(const float2*)&g_P[(size_t)row0 * 2048 + 1536 + col];
        const float2 gB = *(const float2*)&g_P[(size_t)(row0 + 8) * 2048 + 1536 + col];
        float a0 = o[f][0] * inv0 / (1.0f + __expf(-gA.x));
        float a1 = o[f][1] * inv0 / (1.0f + __expf(-gA.y));
        float a2 = o[f][2] * inv1 / (1.0f + __expf(-gB.x));
        float a3 = o[f][3] * inv1 / (1.0f + __expf(-gB.y));
        float h0 = __bfloat162float(__float2bfloat16(a0));
        float h1 = __bfloat162float(__float2bfloat16(a1));
        float h2 = __bfloat162float(__float2bfloat16(a2));
        float h3 = __bfloat162float(__float2bfloat16(a3));
        *(uint32_t*)&g_ah[(size_t)row0 * 512 + col]       = pack_bf16(h0, h1);
        *(uint32_t*)&g_al[(size_t)row0 * 512 + col]       = pack_bf16(a0 - h0, a1 - h1);
        *(uint32_t*)&g_ah[(size_t)(row0 + 8) * 512 + col] = pack_bf16(h2, h3);
        *(uint32_t*)&g_al[(size_t)(row0 + 8) * 512 + col] = pack_bf16(a2 - h2, a3 - h3);
    }
}

// ---------------------------------------------------------------------------
extern "C" void kernel_launch(void* const* d_in, const int* in_sizes, int n_in,
                              void* d_out, int out_size)
{
    const float* x     = (const float*)d_in[0];
    const float* Wq    = (const float*)d_in[1];
    const float* Wk    = (const float*)d_in[2];
    const float* Wv    = (const float*)d_in[3];
    const float* Wg    = (const float*)d_in[4];
    const float* bg    = (const float*)d_in[5];
    const float* Wo    = (const float*)d_in[6];
    const float* mem_k = (const float*)d_in[7];
    const float* mem_v = (const float*)d_in[8];
    const float* freqs = (const float*)d_in[9];
    float* out = (float*)d_out;

    cudaFuncSetAttribute(hmma_gemm, cudaFuncAttributeMaxDynamicSharedMemorySize, GEMM_SMEM);

    void *pxh, *pxl, *pWth, *pWtl, *pWoth, *pWotl, *pah, *pal, *pP;
    cudaGetSymbolAddress(&pxh, g_xh);     cudaGetSymbolAddress(&pxl, g_xl);
    cudaGetSymbolAddress(&pWth, g_Wth);   cudaGetSymbolAddress(&pWtl, g_Wtl);
    cudaGetSymbolAddress(&pWoth, g_Woth); cudaGetSymbolAddress(&pWotl, g_Wotl);
    cudaGetSymbolAddress(&pah, g_ah);     cudaGetSymbolAddress(&pal, g_al);
    cudaGetSymbolAddress(&pP, g_P);

    __nv_bfloat16* xh = (__nv_bfloat16*)pxh;     __nv_bfloat16* xl = (__nv_bfloat16*)pxl;
    __nv_bfloat16* Wth = (__nv_bfloat16*)pWth;   __nv_bfloat16* Wtl = (__nv_bfloat16*)pWtl;
    __nv_bfloat16* Woth = (__nv_bfloat16*)pWoth; __nv_bfloat16* Wotl = (__nv_bfloat16*)pWotl;
    __nv_bfloat16* ah = (__nv_bfloat16*)pah;     __nv_bfloat16* al = (__nv_bfloat16*)pal;
    float* P = (float*)pP;

    prologue<<<PRO_CONV_BLKS + PRO_SIN_BLKS + PRO_WT_BLKS, 256>>>(
        x, freqs, Wq, Wk, Wv, Wg, Wo);

    // proj: n-tiles = 2048/64 = 32, m-tiles = 4096/128 = 32
    hmma_gemm<<<dim3(32, 32), 256, GEMM_SMEM>>>(xh, xl, Wth, Wtl, P, 2048, 512, bg, 1536);

    const int tasks = HH * NN + HH * MEMM;
    prep_kernel<<<(tasks + 7) / 8, 256>>>(mem_k, mem_v);

    attn_kernel<<<dim3(64, 8), 128>>>();

    // out: n-tiles = 512/64 = 8, m-tiles = 32
    hmma_gemm<<<dim3(8, 32), 256, GEMM_SMEM>>>(ah, al, Woth, Wotl, out, 512, 512, nullptr, 0);
}

// round 14
// speedup vs baseline: 1.0003x; 1.0003x over previous
#include <cuda_runtime.h>
#include <cuda_bf16.h>
#include <math.h>
#include <cstdint>

#define NN 4096
#define DD 512
#define HH 8
#define DHH 64
#define MEMM 4
#define WINN 512
#define JJ (NN + MEMM)   /* 4100 */
#define JP 4160          /* padded to multiple of 64 */
#define QK_SCALE 10.0f

// ---------------------------------------------------------------------------
// Warp-MMA helpers (arch-neutral PTX: valid under compute_103)
// ---------------------------------------------------------------------------
__device__ __forceinline__ uint32_t smem_to_u32(const void* smem_ptr) {
    uint32_t addr;
    asm("{ .reg .u64 tmp; cvta.to.shared.u64 tmp, %1; cvt.u32.u64 %0, tmp; }"
        : "=r"(addr) : "l"(smem_ptr));
    return addr;
}
__device__ __forceinline__ void ldsm4(uint32_t& r0, uint32_t& r1, uint32_t& r2, uint32_t& r3,
                                      uint32_t a) {
    asm volatile("ldmatrix.sync.aligned.m8n8.x4.shared.b16 {%0,%1,%2,%3}, [%4];"
                 : "=r"(r0), "=r"(r1), "=r"(r2), "=r"(r3) : "r"(a));
}
__device__ __forceinline__ void ldsm4t(uint32_t& r0, uint32_t& r1, uint32_t& r2, uint32_t& r3,
                                       uint32_t a) {
    asm volatile("ldmatrix.sync.aligned.m8n8.x4.trans.shared.b16 {%0,%1,%2,%3}, [%4];"
                 : "=r"(r0), "=r"(r1), "=r"(r2), "=r"(r3) : "r"(a));
}
__device__ __forceinline__ void mma16816(float* d,
                                         uint32_t a0, uint32_t a1, uint32_t a2, uint32_t a3,
                                         uint32_t b0, uint32_t b1) {
    asm volatile("mma.sync.aligned.m16n8k16.row.col.f32.bf16.bf16.f32 "
                 "{%0,%1,%2,%3}, {%4,%5,%6,%7}, {%8,%9}, {%0,%1,%2,%3};"
                 : "+f"(d[0]), "+f"(d[1]), "+f"(d[2]), "+f"(d[3])
                 : "r"(a0), "r"(a1), "r"(a2), "r"(a3), "r"(b0), "r"(b1));
}
__device__ __forceinline__ uint32_t pack_bf16(float a, float b) {
    __nv_bfloat162 h = __floats2bfloat162_rn(a, b);
    return *(uint32_t*)&h;
}

// ---------------------------------------------------------------------------
// Scratch (device globals)
// ---------------------------------------------------------------------------
__device__ float g_P[NN * 2048];        // fused projection out: [n][Q|K|V|G]
__device__ float g_cos[NN * 64], g_sin[NN * 64];   // rope tables
// bf16 hi/lo splits
__device__ __nv_bfloat16 g_xh[NN * DD],   g_xl[NN * DD];       // x
__device__ __nv_bfloat16 g_Wth[2048 * 512], g_Wtl[2048 * 512]; // [Wq|Wk|Wv|Wg]^T  [n][k]
__device__ __nv_bfloat16 g_Woth[512 * 512], g_Wotl[512 * 512]; // Wo^T [n][k]
__device__ __nv_bfloat16 g_ah[NN * 512],  g_al[NN * 512];      // gated attention out
// attention operands (bf16 hi/lo), zero-padded tails. Q is pre-scaled by QK_SCALE.
__device__ __nv_bfloat16 g_Qh[HH * NN * 64], g_Ql[HH * NN * 64];   // [h][n][d]
__device__ __nv_bfloat16 g_Kh[HH * JP * 64], g_Kl[HH * JP * 64];   // [h][j][d]
__device__ __nv_bfloat16 g_Vh[HH * JP * 64], g_Vl[HH * JP * 64];   // [h][j][d]

// ---------------------------------------------------------------------------
// Merged prologue: conv_split (blocks 0..8191), sincos (8192..9215),
// convert_wt x5 (9216..10495)
// ---------------------------------------------------------------------------
#define PRO_CONV_BLKS  8192
#define PRO_SIN_BLKS   1024
#define PRO_WT_BLKS    1280     /* 5 * 256 */

__global__ void __launch_bounds__(256) prologue(
    const float* __restrict__ x, const float* __restrict__ freqs,
    const float* __restrict__ Wq, const float* __restrict__ Wk,
    const float* __restrict__ Wv, const float* __restrict__ Wg,
    const float* __restrict__ Wo)
{
    const int b = blockIdx.x;
    const int tid = threadIdx.x;
    if (b < PRO_CONV_BLKS) {
        const int i = b * 256 + tid;   // < NN*DD = 2M exactly
        const float v = x[i];
        const __nv_bfloat16 h = __float2bfloat16(v);
        g_xh[i] = h;
        g_xl[i] = __float2bfloat16(v - __bfloat162float(h));
    } else if (b < PRO_CONV_BLKS + PRO_SIN_BLKS) {
        const int i = (b - PRO_CONV_BLKS) * 256 + tid;   // < NN*64 = 256K exactly
        float s, c;
        sincosf(freqs[i], &s, &c);
        g_cos[i] = c;
        g_sin[i] = s;
    } else {
        __shared__ float t[32][33];
        const int bb = b - PRO_CONV_BLKS - PRO_SIN_BLKS;
        const int z = bb >> 8;             // 0..4
        const int tile = bb & 255;
        const float* W = (z == 0) ? Wq : (z == 1) ? Wk : (z == 2) ? Wv : (z == 3) ? Wg : Wo;
        __nv_bfloat16* Dh = (z < 4) ? (g_Wth + (size_t)z * 512 * 512) : g_Woth;
        __nv_bfloat16* Dl = (z < 4) ? (g_Wtl + (size_t)z * 512 * 512) : g_Wotl;
        const int bx = (tile & 15) * 32;   // n
        const int by = (tile >> 4) * 32;   // k
        const int tx = tid & 31, ty = tid >> 5;
#pragma unroll
        for (int i = ty; i < 32; i += 8)
            t[i][tx] = W[(size_t)(by + i) * 512 + bx + tx];
        __syncthreads();
#pragma unroll
        for (int i = ty; i < 32; i += 8) {
            const float v = t[tx][i];
            const __nv_bfloat16 h = __float2bfloat16(v);
            const __nv_bfloat16 l = __float2bfloat16(v - __bfloat162float(h));
            const size_t o = (size_t)(bx + i) * 512 + by + tx;
            Dh[o] = h; Dl[o] = l;
        }
    }
}

// ---------------------------------------------------------------------------
// HMMA split-bf16 GEMM. CTA tile 128(m) x 64(n), warp tile 32x32, 8 warps,
// 3 CTAs/SM. LDG+STS tile fills (unchanged from R10/R12).
// ---------------------------------------------------------------------------
#define SST 72
#define GEMM_SMEM ((2 * 128 + 2 * 64) * SST * 2)   /* 55296 */

__global__ void __launch_bounds__(256, 3) hmma_gemm(
    const __nv_bfloat16* __restrict__ Ah, const __nv_bfloat16* __restrict__ Al,
    const __nv_bfloat16* __restrict__ Bh, const __nv_bfloat16* __restrict__ Bl,
    float* __restrict__ C, int Ntot, int K,
    const float* __restrict__ bias, int bias_off)
{
    extern __shared__ __align__(16) __nv_bfloat16 sm[];
    __nv_bfloat16* sAh = sm;                     // 128 x SST
    __nv_bfloat16* sAl = sm + 128 * SST;         // 128 x SST
    __nv_bfloat16* sBh = sm + 256 * SST;         // 64 x SST
    __nv_bfloat16* sBl = sm + 320 * SST;         // 64 x SST

    const int tid = threadIdx.x;
    const int lane = tid & 31, wid = tid >> 5;
    const int wm = wid & 3, wn = wid >> 2;       // 4 m-warps x 2 n-warps
    const int m0 = blockIdx.y * 128, n0 = blockIdx.x * 64;

    float acc[2][4][4];
#pragma unroll
    for (int i = 0; i < 2; i++)
#pragma unroll
        for (int j = 0; j < 4; j++)
#pragma unroll
            for (int k = 0; k < 4; k++) acc[i][j][k] = 0.0f;

    // loader indices
    const int ar = tid >> 1;               // 0..127
    const int ac = (tid & 1) * 32;         // elems
    const int br = tid >> 2;               // 0..63
    const int bc = (tid & 3) * 16;

    const uint32_t smbase = smem_to_u32(sm);
    const uint32_t afrag = (uint32_t)(((wm * 32 + (lane & 15)) * SST + (lane >> 4) * 8) * 2);
    const uint32_t bfrag = (uint32_t)(((wn * 32 + (lane & 15)) * SST + (lane >> 4) * 8) * 2);
    const uint32_t aAh = smbase + afrag;
    const uint32_t aAl = smbase + 128 * SST * 2 + afrag;
    const uint32_t aBh = smbase + 256 * SST * 2 + bfrag;
    const uint32_t aBl = smbase + 320 * SST * 2 + bfrag;

    for (int kc = 0; kc < K; kc += 64) {
        __syncthreads();
        {
            const size_t ga = (size_t)(m0 + ar) * K + kc + ac;
#pragma unroll
            for (int i = 0; i < 4; i++) {
                *(float4*)&sAh[ar * SST + ac + i * 8] = *(const float4*)&Ah[ga + i * 8];
                *(float4*)&sAl[ar * SST + ac + i * 8] = *(const float4*)&Al[ga + i * 8];
            }
            const size_t gb = (size_t)(n0 + br) * K + kc + bc;
#pragma unroll
            for (int i = 0; i < 2; i++) {
                *(float4*)&sBh[br * SST + bc + i * 8] = *(const float4*)&Bh[gb + i * 8];
                *(float4*)&sBl[br * SST + bc + i * 8] = *(const float4*)&Bl[gb + i * 8];
            }
        }
        __syncthreads();

#pragma unroll
        for (int kk = 0; kk < 4; kk++) {
            const uint32_t ko = kk * 32;
            uint32_t ah[8], al[8], bh[8], bl[8];
            ldsm4(ah[0], ah[1], ah[2], ah[3], aAh + ko);
            ldsm4(ah[4], ah[5], ah[6], ah[7], aAh + ko + 16 * SST * 2);
            ldsm4(al[0], al[1], al[2], al[3], aAl + ko);
            ldsm4(al[4], al[5], al[6], al[7], aAl + ko + 16 * SST * 2);
            ldsm4(bh[0], bh[1], bh[2], bh[3], aBh + ko);
            ldsm4(bh[4], bh[5], bh[6], bh[7], aBh + ko + 16 * SST * 2);
            ldsm4(bl[0], bl[1], bl[2], bl[3], aBl + ko);
            ldsm4(bl[4], bl[5], bl[6], bl[7], aBl + ko + 16 * SST * 2);
#pragma unroll
            for (int bn = 0; bn < 4; bn++) {
                const uint32_t bh0 = bh[(bn >> 1) * 4 + (bn & 1)];
                const uint32_t bh1 = bh[(bn >> 1) * 4 + (bn & 1) + 2];
                const uint32_t bl0 = bl[(bn >> 1) * 4 + (bn & 1)];
                const uint32_t bl1 = bl[(bn >> 1) * 4 + (bn & 1) + 2];
                mma16816(acc[0][bn], ah[0], ah[1], ah[2], ah[3], bh0, bh1);
                mma16816(acc[0][bn], ah[0], ah[1], ah[2], ah[3], bl0, bl1);
                mma16816(acc[0][bn], al[0], al[1], al[2], al[3], bh0, bh1);
                mma16816(acc[1][bn], ah[4], ah[5], ah[6], ah[7], bh0, bh1);
                mma16816(acc[1][bn], ah[4], ah[5], ah[6], ah[7], bl0, bl1);
                mma16816(acc[1][bn], al[4], al[5], al[6], al[7], bh0, bh1);
            }
        }
    }

    const int gid = lane >> 2;
    const int qc = (lane & 3) * 2;
#pragma unroll
    for (int mf = 0; mf < 2; mf++) {
        const int row = m0 + wm * 32 + mf * 16 + gid;
#pragma unroll
        for (int nf = 0; nf < 4; nf++) {
            const int col = n0 + wn * 32 + nf * 8 + qc;
            float2 v0 = make_float2(acc[mf][nf][0], acc[mf][nf][1]);
            float2 v1 = make_float2(acc[mf][nf][2], acc[mf][nf][3]);
            if (bias != nullptr && col >= bias_off) {
                const float b0 = bias[col - bias_off], b1 = bias[col - bias_off + 1];
                v0.x += b0; v0.y += b1;
                v1.x += b0; v1.y += b1;
            }
            *(float2*)&C[(size_t)row * Ntot + col] = v0;
            *(float2*)&C[(size_t)(row + 8) * Ntot + col] = v1;
        }
    }
}

// ---------------------------------------------------------------------------
// prep: per-(h,n) l2norm + RoPE (table-driven), emit bf16 hi/lo Q/K/V.
// Q is pre-scaled by QK_SCALE so attention needs no per-logit scaling.
// ---------------------------------------------------------------------------
__device__ __forceinline__ void split_store(__nv_bfloat16* dh, __nv_bfloat16* dl, float v) {
    __nv_bfloat16 h = __float2bfloat16(v);
    *dh = h;
    *dl = __float2bfloat16(v - __bfloat162float(h));
}

__global__ void __launch_bounds__(256) prep_kernel(
    const float* __restrict__ mem_k, const float* __restrict__ mem_v)
{
    const int warp = (blockIdx.x * blockDim.x + threadIdx.x) >> 5;
    const int lane = threadIdx.x & 31;
    const int total = HH * NN;
    if (warp < total) {
        const int h = warp >> 12;
        const int n = warp & (NN - 1);
        const float c0 = g_cos[n * 64 + lane];
        const float c1 = g_cos[n * 64 + lane + 32];
        const float s0 = g_sin[n * 64 + lane];
        const float s1 = g_sin[n * 64 + lane + 32];
        {
            const float* r = &g_P[n * 2048 + h * 64];
            float t0 = r[lane], t1 = r[lane + 32];
            float ss = t0 * t0 + t1 * t1;
#pragma unroll
            for (int o = 16; o; o >>= 1) ss += __shfl_xor_sync(0xffffffffu, ss, o);
            const float inv = QK_SCALE / fmaxf(sqrtf(ss), 1e-12f);   // scale folded in
            t0 *= inv; t1 *= inv;
            const size_t base = ((size_t)h * NN + n) * 64;
            split_store(&g_Qh[base + lane], &g_Ql[base + lane], t0 * c0 - t1 * s0);
            split_store(&g_Qh[base + lane + 32], &g_Ql[base + lane + 32], t1 * c1 + t0 * s1);
        }
        {
            const float* r = &g_P[n * 2048 + 512 + h * 64];
            float t0 = r[lane], t1 = r[lane + 32];
            float ss = t0 * t0 + t1 * t1;
#pragma unroll
            for (int o = 16; o; o >>= 1) ss += __shfl_xor_sync(0xffffffffu, ss, o);
            const float inv = 1.0f / fmaxf(sqrtf(ss), 1e-12f);
            t0 *= inv; t1 *= inv;
            const size_t base = ((size_t)h * JP + MEMM + n) * 64;
            split_store(&g_Kh[base + lane], &g_Kl[base + lane], t0 * c0 - t1 * s0);
            split_store(&g_Kh[base + lane + 32], &g_Kl[base + lane + 32], t1 * c1 + t0 * s1);
        }
        {
            const float* r = &g_P[n * 2048 + 1024 + h * 64];
            const size_t base = ((size_t)h * JP + MEMM + n) * 64;
            split_store(&g_Vh[base + lane], &g_Vl[base + lane], r[lane]);
            split_store(&g_Vh[base + lane + 32], &g_Vl[base + lane + 32], r[lane + 32]);
        }
    } else if (warp < total + HH * MEMM) {
        const int t = warp - total;
        const int h = t >> 2, m = t & 3;
        const float* r = &mem_k[(h * MEMM + m) * 64];
        float t0 = r[lane], t1 = r[lane + 32];
        float ss = t0 * t0 + t1 * t1;
#pragma unroll
        for (int o = 16; o; o >>= 1) ss += __shfl_xor_sync(0xffffffffu, ss, o);
        const float inv = 1.0f / fmaxf(sqrtf(ss), 1e-12f);
        const size_t kb = ((size_t)h * JP + m) * 64;
        split_store(&g_Kh[kb + lane], &g_Kl[kb + lane], t0 * inv);
        split_store(&g_Kh[kb + lane + 32], &g_Kl[kb + lane + 32], t1 * inv);
        const float* rv = &mem_v[(h * MEMM + m) * 64];
        split_store(&g_Vh[kb + lane], &g_Vl[kb + lane], rv[lane]);
        split_store(&g_Vh[kb + lane + 32], &g_Vl[kb + lane + 32], rv[lane + 32]);
    }
}

// ---------------------------------------------------------------------------
// HMMA banded flash attention, q-tile=128, 8 warps, fused gate epilogue.
// K-step = 128 keys per barrier pair (two 64-key subtiles, same order as R12).
// Dynamic smem: 4 arrays x 128 rows; 2 CTAs/SM (reg-limited, unchanged).
// ---------------------------------------------------------------------------
#define AST 72
#define A_ARR (128 * AST * 2)       /* bytes per array = 18432 */
#define ATTN_SMEM (4 * A_ARR)       /* 73728 */

__global__ void __launch_bounds__(256, 2) attn_kernel()
{
    extern __shared__ __align__(16) char asmem[];

    const int h = blockIdx.y;
    const int iq0 = blockIdx.x * 128;
    const int tid = threadIdx.x;
    const int lane = tid & 31, w = tid >> 5;
    const int gid = lane >> 2;
    const int qc = (lane & 3) * 2;

    const uint32_t smbase = smem_to_u32(asmem);
    const uint32_t sKh = smbase;
    const uint32_t sKl = smbase + A_ARR;
    const uint32_t sVh = smbase + 2 * A_ARR;
    const uint32_t sVl = smbase + 3 * A_ARR;

    // ---- stage Q (128 rows: hi -> array0, lo -> array1), load Q frags once ----
    {
        const int r = tid >> 1, half = (tid & 1) * 32;
        const size_t gq = ((size_t)h * NN + iq0 + r) * 64 + half;
        const int so = (r * AST + half) * 2;
#pragma unroll
        for (int i = 0; i < 4; i++) {
            *(float4*)(asmem + so + i * 16)        = *(const float4*)&g_Qh[gq + i * 8];
            *(float4*)(asmem + A_ARR + so + i * 16) = *(const float4*)&g_Ql[gq + i * 8];
        }
    }
    __syncthreads();
    uint32_t qh[4][4], ql[4][4];
    {
        const int qrow = w * 16 + (lane & 15);           // 0..127
        const uint32_t off = (uint32_t)((qrow * AST + (lane >> 4) * 8) * 2);
#pragma unroll
        for (int ks = 0; ks < 4; ks++) {
            ldsm4(qh[ks][0], qh[ks][1], qh[ks][2], qh[ks][3], sKh + off + ks * 32);
            ldsm4(ql[ks][0], ql[ks][1], ql[ks][2], ql[ks][3], sKl + off + ks * 32);
        }
    }
    __syncthreads();

    float o[8][4];
#pragma unroll
    for (int f = 0; f < 8; f++)
#pragma unroll
        for (int k = 0; k < 4; k++) o[f][k] = 0.0f;
    float m0 = -1e9f, m1 = -1e9f, l0 = 0.0f, l1 = 0.0f;

    const int qpos0 = MEMM + iq0 + w * 16 + gid;
    const int qpos1 = qpos0 + 8;

    int lo = iq0 + MEMM - WINN; if (lo < 0) lo = 0;
    int hi = iq0 + 127 + MEMM + WINN + 1; if (hi > JJ) hi = JJ;
    const int jstart = lo & ~63;

    const uint32_t lmoff = (uint32_t)((((lane & 15)) * AST + (lane >> 4) * 8) * 2);

    for (int j0 = jstart; j0 < hi; j0 += 128) {
        // ---- load up to 128 K/V rows (hi+lo); rows >= JP zero-filled ----
        {
            const int r = tid >> 1;
            const int c = (tid & 1) * 32;
            const int so = (r * AST + c) * 2;
            if (j0 + r < JP) {
                const size_t gb = ((size_t)h * JP + j0 + r) * 64 + c;
#pragma unroll
                for (int i = 0; i < 4; i++) {
                    *(float4*)(asmem + so + i * 16)             = *(const float4*)&g_Kh[gb + i * 8];
                    *(float4*)(asmem + A_ARR + so + i * 16)     = *(const float4*)&g_Kl[gb + i * 8];
                    *(float4*)(asmem + 2 * A_ARR + so + i * 16) = *(const float4*)&g_Vh[gb + i * 8];
                    *(float4*)(asmem + 3 * A_ARR + so + i * 16) = *(const float4*)&g_Vl[gb + i * 8];
                }
            } else {
                const float4 z = make_float4(0.f, 0.f, 0.f, 0.f);
#pragma unroll
                for (int i = 0; i < 4; i++) {
                    *(float4*)(asmem + so + i * 16)             = z;
                    *(float4*)(asmem + A_ARR + so + i * 16)     = z;
                    *(float4*)(asmem + 2 * A_ARR + so + i * 16) = z;
                    *(float4*)(asmem + 3 * A_ARR + so + i * 16) = z;
                }
            }
        }
        __syncthreads();

        for (int jj = 0; jj < 128 && j0 + jj < hi; jj += 64) {
            const int js = j0 + jj;                       // subtile base (CTA-uniform)
            const uint32_t sub = (uint32_t)(jj * AST * 2);

            float s[8][4];
#pragma unroll
            for (int f = 0; f < 8; f++)
#pragma unroll
                for (int k = 0; k < 4; k++) s[f][k] = 0.0f;

#pragma unroll
            for (int ks = 0; ks < 4; ks++) {
#pragma unroll
                for (int g = 0; g < 4; g++) {
                    const uint32_t ba = lmoff + sub + (uint32_t)(g * 16 * AST * 2) + ks * 32;
                    uint32_t kh[4], kl[4];
                    ldsm4(kh[0], kh[1], kh[2], kh[3], sKh + ba);
                    ldsm4(kl[0], kl[1], kl[2], kl[3], sKl + ba);
                    mma16816(s[2 * g],     qh[ks][0], qh[ks][1], qh[ks][2], qh[ks][3], kh[0], kh[2]);
                    mma16816(s[2 * g + 1], qh[ks][0], qh[ks][1], qh[ks][2], qh[ks][3], kh[1], kh[3]);
                    mma16816(s[2 * g],     qh[ks][0], qh[ks][1], qh[ks][2], qh[ks][3], kl[0], kl[2]);
                    mma16816(s[2 * g + 1], qh[ks][0], qh[ks][1], qh[ks][2], qh[ks][3], kl[1], kl[3]);
                    mma16816(s[2 * g],     ql[ks][0], ql[ks][1], ql[ks][2], ql[ks][3], kh[0], kh[2]);
                    mma16816(s[2 * g + 1], ql[ks][0], ql[ks][1], ql[ks][2], ql[ks][3], kh[1], kh[3]);
                }
            }

            // logits are pre-scaled; only masking remains
            const bool needmask = (MEMM + iq0 + 127 - js > WINN) ||
                                  (js + 63 - (MEMM + iq0) > WINN) ||
                                  (js + 64 > JJ);
            if (needmask) {
#pragma unroll
                for (int f = 0; f < 8; f++) {
                    const int k0 = js + 8 * f + qc;
                    const int k1 = k0 + 1;
                    const bool ok00 = (qpos0 - k0 <= WINN) && (k0 - qpos0 <= WINN) && (k0 < JJ);
                    const bool ok01 = (qpos0 - k1 <= WINN) && (k1 - qpos0 <= WINN) && (k1 < JJ);
                    const bool ok10 = (qpos1 - k0 <= WINN) && (k0 - qpos1 <= WINN) && (k0 < JJ);
                    const bool ok11 = (qpos1 - k1 <= WINN) && (k1 - qpos1 <= WINN) && (k1 < JJ);
                    if (!ok00) s[f][0] = -1e30f;
                    if (!ok01) s[f][1] = -1e30f;
                    if (!ok10) s[f][2] = -1e30f;
                    if (!ok11) s[f][3] = -1e30f;
                }
            }

            float mx0 = -1e30f, mx1 = -1e30f;
#pragma unroll
            for (int f = 0; f < 8; f++) {
                mx0 = fmaxf(mx0, fmaxf(s[f][0], s[f][1]));
                mx1 = fmaxf(mx1, fmaxf(s[f][2], s[f][3]));
            }
            mx0 = fmaxf(mx0, __shfl_xor_sync(0xffffffffu, mx0, 1));
            mx0 = fmaxf(mx0, __shfl_xor_sync(0xffffffffu, mx0, 2));
            mx1 = fmaxf(mx1, __shfl_xor_sync(0xffffffffu, mx1, 1));
            mx1 = fmaxf(mx1, __shfl_xor_sync(0xffffffffu, mx1, 2));
            const float mn0 = fmaxf(m0, mx0), mn1 = fmaxf(m1, mx1);
            const float corr0 = __expf(m0 - mn0), corr1 = __expf(m1 - mn1);
            m0 = mn0; m1 = mn1;

            float ls0 = 0.0f, ls1 = 0.0f;
#pragma unroll
            for (int f = 0; f < 8; f++) {
                s[f][0] = __expf(s[f][0] - mn0);
                s[f][1] = __expf(s[f][1] - mn0);
                s[f][2] = __expf(s[f][2] - mn1);
                s[f][3] = __expf(s[f][3] - mn1);
                ls0 += s[f][0] + s[f][1];
                ls1 += s[f][2] + s[f][3];
            }
            ls0 += __shfl_xor_sync(0xffffffffu, ls0, 1);
            ls0 += __shfl_xor_sync(0xffffffffu, ls0, 2);
            ls1 += __shfl_xor_sync(0xffffffffu, ls1, 1);
            ls1 += __shfl_xor_sync(0xffffffffu, ls1, 2);
            l0 = l0 * corr0 + ls0;
            l1 = l1 * corr1 + ls1;
#pragma unroll
            for (int f = 0; f < 8; f++) {
                o[f][0] *= corr0; o[f][1] *= corr0;
                o[f][2] *= corr1; o[f][3] *= corr1;
            }

            uint32_t pah[4][4], pal[4][4];
#pragma unroll
            for (int g = 0; g < 4; g++) {
                float p00 = s[2 * g][0],     p01 = s[2 * g][1];
                float p10 = s[2 * g][2],     p11 = s[2 * g][3];
                float p20 = s[2 * g + 1][0], p21 = s[2 * g + 1][1];
                float p30 = s[2 * g + 1][2], p31 = s[2 * g + 1][3];
                float h00 = __bfloat162float(__float2bfloat16(p00));
                float h01 = __bfloat162float(__float2bfloat16(p01));
                float h10 = __bfloat162float(__float2bfloat16(p10));
                float h11 = __bfloat162float(__float2bfloat16(p11));
                float h20 = __bfloat162float(__float2bfloat16(p20));
                float h21 = __bfloat162float(__float2bfloat16(p21));
                float h30 = __bfloat162float(__float2bfloat16(p30));
                float h31 = __bfloat162float(__float2bfloat16(p31));
                pah[g][0] = pack_bf16(h00, h01);
                pah[g][1] = pack_bf16(h10, h11);
                pah[g][2] = pack_bf16(h20, h21);
                pah[g][3] = pack_bf16(h30, h31);
                pal[g][0] = pack_bf16(p00 - h00, p01 - h01);
                pal[g][1] = pack_bf16(p10 - h10, p11 - h11);
                pal[g][2] = pack_bf16(p20 - h20, p21 - h21);
                pal[g][3] = pack_bf16(p30 - h30, p31 - h31);
            }

#pragma unroll
            for (int g = 0; g < 4; g++) {
#pragma unroll
                for (int dg = 0; dg < 4; dg++) {
                    const uint32_t ba = lmoff + sub + (uint32_t)(g * 16 * AST * 2) + dg * 32;
                    uint32_t vh[4], vl[4];
                    ldsm4t(vh[0], vh[1], vh[2], vh[3], sVh + ba);
                    ldsm4t(vl[0], vl[1], vl[2], vl[3], sVl + ba);
                    mma16816(o[2 * dg],     pah[g][0], pah[g][1], pah[g][2], pah[g][3], vh[0], vh[1]);
                    mma16816(o[2 * dg + 1], pah[g][0], pah[g][1], pah[g][2], pah[g][3], vh[2], vh[3]);
                    mma16816(o[2 * dg],     pah[g][0], pah[g][1], pah[g][2], pah[g][3], vl[0], vl[1]);
                    mma16816(o[2 * dg + 1], pah[g][0], pah[g][1], pah[g][2], pah[g][3], vl[2], vl[3]);
                    mma16816(o[2 * dg],     pal[g][0], pal[g][1], pal[g][2], pal[g][3], vh[0], vh[1]);
                    mma16816(o[2 * dg + 1], pal[g][0], pal[g][1], pal[g][2], pal[g][3], vh[2], vh[3]);
                }
            }
        }
        __syncthreads();   // both subtiles read; buffer free for next 128 rows
    }

    // ---- epilogue: normalize, gate (sigmoid), bf16 split, write ----
    const float inv0 = 1.0f / l0, inv1 = 1.0f / l1;
    const int row0 = iq0 + w * 16 + gid;
#pragma unroll
    for (int f = 0; f < 8; f++) {
        const int col = h * 64 + 8 * f + qc;
        const float2 gA = *(const float2*)&g_P[(size_t)row0 * 2048 + 1536 + col];
        const float2 gB = *(const float2*)&g_P[(size_t)(row0 + 8) * 2048 + 1536 + col];
        float a0 = o[f][0] * inv0 / (1.0f + __expf(-gA.x));
        float a1 = o[f][1] * inv0 / (1.0f + __expf(-gA.y));
        float a2 = o[f][2] * inv1 / (1.0f + __expf(-gB.x));
        float a3 = o[f][3] * inv1 / (1.0f + __expf(-gB.y));
        float h0 = __bfloat162float(__float2bfloat16(a0));
        float h1 = __bfloat162float(__float2bfloat16(a1));
        float h2 = __bfloat162float(__float2bfloat16(a2));
        float h3 = __bfloat162float(__float2bfloat16(a3));
        *(uint32_t*)&g_ah[(size_t)row0 * 512 + col]       = pack_bf16(h0, h1);
        *(uint32_t*)&g_al[(size_t)row0 * 512 + col]       = pack_bf16(a0 - h0, a1 - h1);
        *(uint32_t*)&g_ah[(size_t)(row0 + 8) * 512 + col] = pack_bf16(h2, h3);
        *(uint32_t*)&g_al[(size_t)(row0 + 8) * 512 + col] = pack_bf16(a2 - h2, a3 - h3);
    }
}

// ---------------------------------------------------------------------------
extern "C" void kernel_launch(void* const* d_in, const int* in_sizes, int n_in,
                              void* d_out, int out_size)
{
    const float* x     = (const float*)d_in[0];
    const float* Wq    = (const float*)d_in[1];
    const float* Wk    = (const float*)d_in[2];
    const float* Wv    = (const float*)d_in[3];
    const float* Wg    = (const float*)d_in[4];
    const float* bg    = (const float*)d_in[5];
    const float* Wo    = (const float*)d_in[6];
    const float* mem_k = (const float*)d_in[7];
    const float* mem_v = (const float*)d_in[8];
    const float* freqs = (const float*)d_in[9];
    float* out = (float*)d_out;

    cudaFuncSetAttribute(hmma_gemm, cudaFuncAttributeMaxDynamicSharedMemorySize, GEMM_SMEM);
    cudaFuncSetAttribute(attn_kernel, cudaFuncAttributeMaxDynamicSharedMemorySize, ATTN_SMEM);

    void *pxh, *pxl, *pWth, *pWtl, *pWoth, *pWotl, *pah, *pal, *pP;
    cudaGetSymbolAddress(&pxh, g_xh);     cudaGetSymbolAddress(&pxl, g_xl);
    cudaGetSymbolAddress(&pWth, g_Wth);   cudaGetSymbolAddress(&pWtl, g_Wtl);
    cudaGetSymbolAddress(&pWoth, g_Woth); cudaGetSymbolAddress(&pWotl, g_Wotl);
    cudaGetSymbolAddress(&pah, g_ah);     cudaGetSymbolAddress(&pal, g_al);
    cudaGetSymbolAddress(&pP, g_P);

    __nv_bfloat16* xh = (__nv_bfloat16*)pxh;     __nv_bfloat16* xl = (__nv_bfloat16*)pxl;
    __nv_bfloat16* Wth = (__nv_bfloat16*)pWth;   __nv_bfloat16* Wtl = (__nv_bfloat16*)pWtl;
    __nv_bfloat16* Woth = (__nv_bfloat16*)pWoth; __nv_bfloat16* Wotl = (__nv_bfloat16*)pWotl;
    __nv_bfloat16* ah = (__nv_bfloat16*)pah;     __nv_bfloat16* al = (__nv_bfloat16*)pal;
    float* P = (float*)pP;

    prologue<<<PRO_CONV_BLKS + PRO_SIN_BLKS + PRO_WT_BLKS, 256>>>(
        x, freqs, Wq, Wk, Wv, Wg, Wo);

    // proj: n-tiles = 2048/64 = 32, m-tiles = 4096/128 = 32
    hmma_gemm<<<dim3(32, 32), 256, GEMM_SMEM>>>(xh, xl, Wth, Wtl, P, 2048, 512, bg, 1536);

    const int tasks = HH * NN + HH * MEMM;
    prep_kernel<<<(tasks + 7) / 8, 256>>>(mem_k, mem_v);

    attn_kernel<<<dim3(32, 8), 256, ATTN_SMEM>>>();

    // out: n-tiles = 512/64 = 8, m-tiles = 32
    hmma_gemm<<<dim3(8, 32), 256, GEMM_SMEM>>>(ah, al, Woth, Wotl, out, 512, 512, nullptr, 0);
}

// round 15
// speedup vs baseline: 1.0534x; 1.0530x over previous
#include <cuda_runtime.h>
#include <cuda_bf16.h>
#include <math.h>
#include <cstdint>

#define NN 4096
#define DD 512
#define HH 8
#define DHH 64
#define MEMM 4
#define WINN 512
#define JJ (NN + MEMM)   /* 4100 */
#define JP 4160          /* padded to multiple of 64 */
#define QK_SCALE 10.0f

// ---------------------------------------------------------------------------
// Warp-MMA helpers (arch-neutral PTX: valid under compute_103)
// ---------------------------------------------------------------------------
__device__ __forceinline__ uint32_t smem_to_u32(const void* smem_ptr) {
    uint32_t addr;
    asm("{ .reg .u64 tmp; cvta.to.shared.u64 tmp, %1; cvt.u32.u64 %0, tmp; }"
        : "=r"(addr) : "l"(smem_ptr));
    return addr;
}
__device__ __forceinline__ void ldsm4(uint32_t& r0, uint32_t& r1, uint32_t& r2, uint32_t& r3,
                                      uint32_t a) {
    asm volatile("ldmatrix.sync.aligned.m8n8.x4.shared.b16 {%0,%1,%2,%3}, [%4];"
                 : "=r"(r0), "=r"(r1), "=r"(r2), "=r"(r3) : "r"(a));
}
__device__ __forceinline__ void ldsm4t(uint32_t& r0, uint32_t& r1, uint32_t& r2, uint32_t& r3,
                                       uint32_t a) {
    asm volatile("ldmatrix.sync.aligned.m8n8.x4.trans.shared.b16 {%0,%1,%2,%3}, [%4];"
                 : "=r"(r0), "=r"(r1), "=r"(r2), "=r"(r3) : "r"(a));
}
__device__ __forceinline__ void mma16816(float* d,
                                         uint32_t a0, uint32_t a1, uint32_t a2, uint32_t a3,
                                         uint32_t b0, uint32_t b1) {
    asm volatile("mma.sync.aligned.m16n8k16.row.col.f32.bf16.bf16.f32 "
                 "{%0,%1,%2,%3}, {%4,%5,%6,%7}, {%8,%9}, {%0,%1,%2,%3};"
                 : "+f"(d[0]), "+f"(d[1]), "+f"(d[2]), "+f"(d[3])
                 : "r"(a0), "r"(a1), "r"(a2), "r"(a3), "r"(b0), "r"(b1));
}
__device__ __forceinline__ uint32_t pack_bf16(float a, float b) {
    __nv_bfloat162 h = __floats2bfloat162_rn(a, b);
    return *(uint32_t*)&h;
}
// split a float pair: hi = rn-rounded bf16 pair (packed), lo = residual pair (packed).
// hi floats reconstructed exactly via bit surgery (bf16->fp32 is bits<<16).
__device__ __forceinline__ void split_pair(float a, float b, uint32_t& hi, uint32_t& lo) {
    hi = pack_bf16(a, b);
    const float ha = __uint_as_float(hi << 16);
    const float hb = __uint_as_float(hi & 0xffff0000u);
    lo = pack_bf16(a - ha, b - hb);
}

// ---------------------------------------------------------------------------
// Scratch (device globals)
// ---------------------------------------------------------------------------
__device__ float g_P[NN * 2048];        // fused projection out: [n][Q|K|V|G]
__device__ float g_cos[NN * 64], g_sin[NN * 64];   // rope tables
// bf16 hi/lo splits
__device__ __nv_bfloat16 g_xh[NN * DD],   g_xl[NN * DD];       // x
__device__ __nv_bfloat16 g_Wth[2048 * 512], g_Wtl[2048 * 512]; // [Wq|Wk|Wv|Wg]^T  [n][k]
__device__ __nv_bfloat16 g_Woth[512 * 512], g_Wotl[512 * 512]; // Wo^T [n][k]
__device__ __nv_bfloat16 g_ah[NN * 512],  g_al[NN * 512];      // gated attention out
// attention operands (bf16 hi/lo), zero-padded tails. Q is pre-scaled by QK_SCALE.
__device__ __nv_bfloat16 g_Qh[HH * NN * 64], g_Ql[HH * NN * 64];   // [h][n][d]
__device__ __nv_bfloat16 g_Kh[HH * JP * 64], g_Kl[HH * JP * 64];   // [h][j][d]
__device__ __nv_bfloat16 g_Vh[HH * JP * 64], g_Vl[HH * JP * 64];   // [h][j][d]

// ---------------------------------------------------------------------------
// Merged prologue: conv_split (blocks 0..8191), sincos (8192..9215),
// convert_wt x5 (9216..10495)
// ---------------------------------------------------------------------------
#define PRO_CONV_BLKS  8192
#define PRO_SIN_BLKS   1024
#define PRO_WT_BLKS    1280     /* 5 * 256 */

__global__ void __launch_bounds__(256) prologue(
    const float* __restrict__ x, const float* __restrict__ freqs,
    const float* __restrict__ Wq, const float* __restrict__ Wk,
    const float* __restrict__ Wv, const float* __restrict__ Wg,
    const float* __restrict__ Wo)
{
    const int b = blockIdx.x;
    const int tid = threadIdx.x;
    if (b < PRO_CONV_BLKS) {
        const int i = b * 256 + tid;   // < NN*DD = 2M exactly
        const float v = x[i];
        const __nv_bfloat16 h = __float2bfloat16(v);
        g_xh[i] = h;
        g_xl[i] = __float2bfloat16(v - __bfloat162float(h));
    } else if (b < PRO_CONV_BLKS + PRO_SIN_BLKS) {
        const int i = (b - PRO_CONV_BLKS) * 256 + tid;   // < NN*64 = 256K exactly
        float s, c;
        sincosf(freqs[i], &s, &c);
        g_cos[i] = c;
        g_sin[i] = s;
    } else {
        __shared__ float t[32][33];
        const int bb = b - PRO_CONV_BLKS - PRO_SIN_BLKS;
        const int z = bb >> 8;             // 0..4
        const int tile = bb & 255;
        const float* W = (z == 0) ? Wq : (z == 1) ? Wk : (z == 2) ? Wv : (z == 3) ? Wg : Wo;
        __nv_bfloat16* Dh = (z < 4) ? (g_Wth + (size_t)z * 512 * 512) : g_Woth;
        __nv_bfloat16* Dl = (z < 4) ? (g_Wtl + (size_t)z * 512 * 512) : g_Wotl;
        const int bx = (tile & 15) * 32;   // n
        const int by = (tile >> 4) * 32;   // k
        const int tx = tid & 31, ty = tid >> 5;
#pragma unroll
        for (int i = ty; i < 32; i += 8)
            t[i][tx] = W[(size_t)(by + i) * 512 + bx + tx];
        __syncthreads();
#pragma unroll
        for (int i = ty; i < 32; i += 8) {
            const float v = t[tx][i];
            const __nv_bfloat16 h = __float2bfloat16(v);
            const __nv_bfloat16 l = __float2bfloat16(v - __bfloat162float(h));
            const size_t o = (size_t)(bx + i) * 512 + by + tx;
            Dh[o] = h; Dl[o] = l;
        }
    }
}

// ---------------------------------------------------------------------------
// HMMA split-bf16 GEMM. CTA tile 128(m) x 64(n), warp tile 32x32, 8 warps,
// 3 CTAs/SM. LDG+STS tile fills (unchanged from R10/R12).
// ---------------------------------------------------------------------------
#define SST 72
#define GEMM_SMEM ((2 * 128 + 2 * 64) * SST * 2)   /* 55296 */

__global__ void __launch_bounds__(256, 3) hmma_gemm(
    const __nv_bfloat16* __restrict__ Ah, const __nv_bfloat16* __restrict__ Al,
    const __nv_bfloat16* __restrict__ Bh, const __nv_bfloat16* __restrict__ Bl,
    float* __restrict__ C, int Ntot, int K,
    const float* __restrict__ bias, int bias_off)
{
    extern __shared__ __align__(16) __nv_bfloat16 sm[];
    __nv_bfloat16* sAh = sm;                     // 128 x SST
    __nv_bfloat16* sAl = sm + 128 * SST;         // 128 x SST
    __nv_bfloat16* sBh = sm + 256 * SST;         // 64 x SST
    __nv_bfloat16* sBl = sm + 320 * SST;         // 64 x SST

    const int tid = threadIdx.x;
    const int lane = tid & 31, wid = tid >> 5;
    const int wm = wid & 3, wn = wid >> 2;       // 4 m-warps x 2 n-warps
    const int m0 = blockIdx.y * 128, n0 = blockIdx.x * 64;

    float acc[2][4][4];
#pragma unroll
    for (int i = 0; i < 2; i++)
#pragma unroll
        for (int j = 0; j < 4; j++)
#pragma unroll
            for (int k = 0; k < 4; k++) acc[i][j][k] = 0.0f;

    // loader indices
    const int ar = tid >> 1;               // 0..127
    const int ac = (tid & 1) * 32;         // elems
    const int br = tid >> 2;               // 0..63
    const int bc = (tid & 3) * 16;

    const uint32_t smbase = smem_to_u32(sm);
    const uint32_t afrag = (uint32_t)(((wm * 32 + (lane & 15)) * SST + (lane >> 4) * 8) * 2);
    const uint32_t bfrag = (uint32_t)(((wn * 32 + (lane & 15)) * SST + (lane >> 4) * 8) * 2);
    const uint32_t aAh = smbase + afrag;
    const uint32_t aAl = smbase + 128 * SST * 2 + afrag;
    const uint32_t aBh = smbase + 256 * SST * 2 + bfrag;
    const uint32_t aBl = smbase + 320 * SST * 2 + bfrag;

    for (int kc = 0; kc < K; kc += 64) {
        __syncthreads();
        {
            const size_t ga = (size_t)(m0 + ar) * K + kc + ac;
#pragma unroll
            for (int i = 0; i < 4; i++) {
                *(float4*)&sAh[ar * SST + ac + i * 8] = *(const float4*)&Ah[ga + i * 8];
                *(float4*)&sAl[ar * SST + ac + i * 8] = *(const float4*)&Al[ga + i * 8];
            }
            const size_t gb = (size_t)(n0 + br) * K + kc + bc;
#pragma unroll
            for (int i = 0; i < 2; i++) {
                *(float4*)&sBh[br * SST + bc + i * 8] = *(const float4*)&Bh[gb + i * 8];
                *(float4*)&sBl[br * SST + bc + i * 8] = *(const float4*)&Bl[gb + i * 8];
            }
        }
        __syncthreads();

#pragma unroll
        for (int kk = 0; kk < 4; kk++) {
            const uint32_t ko = kk * 32;
            uint32_t ah[8], al[8], bh[8], bl[8];
            ldsm4(ah[0], ah[1], ah[2], ah[3], aAh + ko);
            ldsm4(ah[4], ah[5], ah[6], ah[7], aAh + ko + 16 * SST * 2);
            ldsm4(al[0], al[1], al[2], al[3], aAl + ko);
            ldsm4(al[4], al[5], al[6], al[7], aAl + ko + 16 * SST * 2);
            ldsm4(bh[0], bh[1], bh[2], bh[3], aBh + ko);
            ldsm4(bh[4], bh[5], bh[6], bh[7], aBh + ko + 16 * SST * 2);
            ldsm4(bl[0], bl[1], bl[2], bl[3], aBl + ko);
            ldsm4(bl[4], bl[5], bl[6], bl[7], aBl + ko + 16 * SST * 2);
#pragma unroll
            for (int bn = 0; bn < 4; bn++) {
                const uint32_t bh0 = bh[(bn >> 1) * 4 + (bn & 1)];
                const uint32_t bh1 = bh[(bn >> 1) * 4 + (bn & 1) + 2];
                const uint32_t bl0 = bl[(bn >> 1) * 4 + (bn & 1)];
                const uint32_t bl1 = bl[(bn >> 1) * 4 + (bn & 1) + 2];
                mma16816(acc[0][bn], ah[0], ah[1], ah[2], ah[3], bh0, bh1);
                mma16816(acc[0][bn], ah[0], ah[1], ah[2], ah[3], bl0, bl1);
                mma16816(acc[0][bn], al[0], al[1], al[2], al[3], bh0, bh1);
                mma16816(acc[1][bn], ah[4], ah[5], ah[6], ah[7], bh0, bh1);
                mma16816(acc[1][bn], ah[4], ah[5], ah[6], ah[7], bl0, bl1);
                mma16816(acc[1][bn], al[4], al[5], al[6], al[7], bh0, bh1);
            }
        }
    }

    const int gid = lane >> 2;
    const int qc = (lane & 3) * 2;
#pragma unroll
    for (int mf = 0; mf < 2; mf++) {
        const int row = m0 + wm * 32 + mf * 16 + gid;
#pragma unroll
        for (int nf = 0; nf < 4; nf++) {
            const int col = n0 + wn * 32 + nf * 8 + qc;
            float2 v0 = make_float2(acc[mf][nf][0], acc[mf][nf][1]);
            float2 v1 = make_float2(acc[mf][nf][2], acc[mf][nf][3]);
            if (bias != nullptr && col >= bias_off) {
                const float b0 = bias[col - bias_off], b1 = bias[col - bias_off + 1];
                v0.x += b0; v0.y += b1;
                v1.x += b0; v1.y += b1;
            }
            *(float2*)&C[(size_t)row * Ntot + col] = v0;
            *(float2*)&C[(size_t)(row + 8) * Ntot + col] = v1;
        }
    }
}

// ---------------------------------------------------------------------------
// prep: per-(h,n) l2norm + RoPE (table-driven), emit bf16 hi/lo Q/K/V.
// Q is pre-scaled by QK_SCALE so attention needs no per-logit scaling.
// ---------------------------------------------------------------------------
__device__ __forceinline__ void split_store(__nv_bfloat16* dh, __nv_bfloat16* dl, float v) {
    __nv_bfloat16 h = __float2bfloat16(v);
    *dh = h;
    *dl = __float2bfloat16(v - __bfloat162float(h));
}

__global__ void __launch_bounds__(256) prep_kernel(
    const float* __restrict__ mem_k, const float* __restrict__ mem_v)
{
    const int warp = (blockIdx.x * blockDim.x + threadIdx.x) >> 5;
    const int lane = threadIdx.x & 31;
    const int total = HH * NN;
    if (warp < total) {
        const int h = warp >> 12;
        const int n = warp & (NN - 1);
        const float c0 = g_cos[n * 64 + lane];
        const float c1 = g_cos[n * 64 + lane + 32];
        const float s0 = g_sin[n * 64 + lane];
        const float s1 = g_sin[n * 64 + lane + 32];
        {
            const float* r = &g_P[n * 2048 + h * 64];
            float t0 = r[lane], t1 = r[lane + 32];
            float ss = t0 * t0 + t1 * t1;
#pragma unroll
            for (int o = 16; o; o >>= 1) ss += __shfl_xor_sync(0xffffffffu, ss, o);
            const float inv = QK_SCALE / fmaxf(sqrtf(ss), 1e-12f);   // scale folded in
            t0 *= inv; t1 *= inv;
            const size_t base = ((size_t)h * NN + n) * 64;
            split_store(&g_Qh[base + lane], &g_Ql[base + lane], t0 * c0 - t1 * s0);
            split_store(&g_Qh[base + lane + 32], &g_Ql[base + lane + 32], t1 * c1 + t0 * s1);
        }
        {
            const float* r = &g_P[n * 2048 + 512 + h * 64];
            float t0 = r[lane], t1 = r[lane + 32];
            float ss = t0 * t0 + t1 * t1;
#pragma unroll
            for (int o = 16; o; o >>= 1) ss += __shfl_xor_sync(0xffffffffu, ss, o);
            const float inv = 1.0f / fmaxf(sqrtf(ss), 1e-12f);
            t0 *= inv; t1 *= inv;
            const size_t base = ((size_t)h * JP + MEMM + n) * 64;
            split_store(&g_Kh[base + lane], &g_Kl[base + lane], t0 * c0 - t1 * s0);
            split_store(&g_Kh[base + lane + 32], &g_Kl[base + lane + 32], t1 * c1 + t0 * s1);
        }
        {
            const float* r = &g_P[n * 2048 + 1024 + h * 64];
            const size_t base = ((size_t)h * JP + MEMM + n) * 64;
            split_store(&g_Vh[base + lane], &g_Vl[base + lane], r[lane]);
            split_store(&g_Vh[base + lane + 32], &g_Vl[base + lane + 32], r[lane + 32]);
        }
    } else if (warp < total + HH * MEMM) {
        const int t = warp - total;
        const int h = t >> 2, m = t & 3;
        const float* r = &mem_k[(h * MEMM + m) * 64];
        float t0 = r[lane], t1 = r[lane + 32];
        float ss = t0 * t0 + t1 * t1;
#pragma unroll
        for (int o = 16; o; o >>= 1) ss += __shfl_xor_sync(0xffffffffu, ss, o);
        const float inv = 1.0f / fmaxf(sqrtf(ss), 1e-12f);
        const size_t kb = ((size_t)h * JP + m) * 64;
        split_store(&g_Kh[kb + lane], &g_Kl[kb + lane], t0 * inv);
        split_store(&g_Kh[kb + lane + 32], &g_Kl[kb + lane + 32], t1 * inv);
        const float* rv = &mem_v[(h * MEMM + m) * 64];
        split_store(&g_Vh[kb + lane], &g_Vl[kb + lane], rv[lane]);
        split_store(&g_Vh[kb + lane + 32], &g_Vl[kb + lane + 32], rv[lane + 32]);
    }
}

// ---------------------------------------------------------------------------
// HMMA banded flash attention, q-tile=128, 8 warps, fused gate epilogue.
// Exact R12 structure; P-split uses bit-trick hi extraction (fewer ALU ops).
// ---------------------------------------------------------------------------
#define AST 72

__global__ void __launch_bounds__(256, 2) attn_kernel()
{
    __shared__ __align__(16) __nv_bfloat16 sm4[4][64 * AST];

    const int h = blockIdx.y;
    const int iq0 = blockIdx.x * 128;
    const int tid = threadIdx.x;
    const int lane = tid & 31, w = tid >> 5;
    const int gid = lane >> 2;
    const int qc = (lane & 3) * 2;

    const uint32_t sKh = smem_to_u32(sm4[0]);
    const uint32_t sKl = smem_to_u32(sm4[1]);
    const uint32_t sVh = smem_to_u32(sm4[2]);
    const uint32_t sVl = smem_to_u32(sm4[3]);

    // ---- stage Q (128 rows), load Q frags once ----
    {
        const int r = tid >> 1, half = (tid & 1) * 32;
        const size_t gq = ((size_t)h * NN + iq0 + r) * 64 + half;
        const int so = (r & 63) * AST + half;
        __nv_bfloat16* dsth = (r < 64) ? sm4[0] : sm4[1];
        __nv_bfloat16* dstl = (r < 64) ? sm4[2] : sm4[3];
#pragma unroll
        for (int i = 0; i < 4; i++) {
            *(float4*)&dsth[so + i * 8] = *(const float4*)&g_Qh[gq + i * 8];
            *(float4*)&dstl[so + i * 8] = *(const float4*)&g_Ql[gq + i * 8];
        }
    }
    __syncthreads();
    uint32_t qh[4][4], ql[4][4];
    {
        const int qrow = w * 16 + (lane & 15);
        const uint32_t off = (uint32_t)(((qrow & 63) * AST + (lane >> 4) * 8) * 2);
        const uint32_t bh = ((qrow < 64) ? sKh : sKl) + off;
        const uint32_t bl = ((qrow < 64) ? sVh : sVl) + off;
#pragma unroll
        for (int ks = 0; ks < 4; ks++) {
            ldsm4(qh[ks][0], qh[ks][1], qh[ks][2], qh[ks][3], bh + ks * 32);
            ldsm4(ql[ks][0], ql[ks][1], ql[ks][2], ql[ks][3], bl + ks * 32);
        }
    }
    __syncthreads();

    float o[8][4];
#pragma unroll
    for (int f = 0; f < 8; f++)
#pragma unroll
        for (int k = 0; k < 4; k++) o[f][k] = 0.0f;
    float m0 = -1e9f, m1 = -1e9f, l0 = 0.0f, l1 = 0.0f;

    const int qpos0 = MEMM + iq0 + w * 16 + gid;
    const int qpos1 = qpos0 + 8;

    int lo = iq0 + MEMM - WINN; if (lo < 0) lo = 0;
    int hi = iq0 + 127 + MEMM + WINN + 1; if (hi > JJ) hi = JJ;

    const uint32_t lmoff = (uint32_t)((((lane & 15)) * AST + (lane >> 4) * 8) * 2);

    for (int j0 = lo & ~63; j0 < hi; j0 += 64) {
        {
            const int r = tid >> 2;
            const int c = (tid & 3) * 16;
            const size_t gb = ((size_t)h * JP + j0 + r) * 64 + c;
            const int so = r * AST + c;
#pragma unroll
            for (int i = 0; i < 2; i++) {
                *(float4*)&sm4[0][so + i * 8] = *(const float4*)&g_Kh[gb + i * 8];
                *(float4*)&sm4[1][so + i * 8] = *(const float4*)&g_Kl[gb + i * 8];
                *(float4*)&sm4[2][so + i * 8] = *(const float4*)&g_Vh[gb + i * 8];
                *(float4*)&sm4[3][so + i * 8] = *(const float4*)&g_Vl[gb + i * 8];
            }
        }
        __syncthreads();

        float s[8][4];
#pragma unroll
        for (int f = 0; f < 8; f++)
#pragma unroll
            for (int k = 0; k < 4; k++) s[f][k] = 0.0f;

#pragma unroll
        for (int ks = 0; ks < 4; ks++) {
#pragma unroll
            for (int g = 0; g < 4; g++) {
                const uint32_t ba = lmoff + (uint32_t)(g * 16 * AST * 2) + ks * 32;
                uint32_t kh[4], kl[4];
                ldsm4(kh[0], kh[1], kh[2], kh[3], sKh + ba);
                ldsm4(kl[0], kl[1], kl[2], kl[3], sKl + ba);
                mma16816(s[2 * g],     qh[ks][0], qh[ks][1], qh[ks][2], qh[ks][3], kh[0], kh[2]);
                mma16816(s[2 * g + 1], qh[ks][0], qh[ks][1], qh[ks][2], qh[ks][3], kh[1], kh[3]);
                mma16816(s[2 * g],     qh[ks][0], qh[ks][1], qh[ks][2], qh[ks][3], kl[0], kl[2]);
                mma16816(s[2 * g + 1], qh[ks][0], qh[ks][1], qh[ks][2], qh[ks][3], kl[1], kl[3]);
                mma16816(s[2 * g],     ql[ks][0], ql[ks][1], ql[ks][2], ql[ks][3], kh[0], kh[2]);
                mma16816(s[2 * g + 1], ql[ks][0], ql[ks][1], ql[ks][2], ql[ks][3], kh[1], kh[3]);
            }
        }

        // logits are pre-scaled; only masking remains
        const bool needmask = (MEMM + iq0 + 127 - j0 > WINN) ||
                              (j0 + 63 - (MEMM + iq0) > WINN) ||
                              (j0 + 64 > JJ);
        if (needmask) {
#pragma unroll
            for (int f = 0; f < 8; f++) {
                const int k0 = j0 + 8 * f + qc;
                const int k1 = k0 + 1;
                const bool ok00 = (qpos0 - k0 <= WINN) && (k0 - qpos0 <= WINN) && (k0 < JJ);
                const bool ok01 = (qpos0 - k1 <= WINN) && (k1 - qpos0 <= WINN) && (k1 < JJ);
                const bool ok10 = (qpos1 - k0 <= WINN) && (k0 - qpos1 <= WINN) && (k0 < JJ);
                const bool ok11 = (qpos1 - k1 <= WINN) && (k1 - qpos1 <= WINN) && (k1 < JJ);
                if (!ok00) s[f][0] = -1e30f;
                if (!ok01) s[f][1] = -1e30f;
                if (!ok10) s[f][2] = -1e30f;
                if (!ok11) s[f][3] = -1e30f;
            }
        }

        float mx0 = -1e30f, mx1 = -1e30f;
#pragma unroll
        for (int f = 0; f < 8; f++) {
            mx0 = fmaxf(mx0, fmaxf(s[f][0], s[f][1]));
            mx1 = fmaxf(mx1, fmaxf(s[f][2], s[f][3]));
        }
        mx0 = fmaxf(mx0, __shfl_xor_sync(0xffffffffu, mx0, 1));
        mx0 = fmaxf(mx0, __shfl_xor_sync(0xffffffffu, mx0, 2));
        mx1 = fmaxf(mx1, __shfl_xor_sync(0xffffffffu, mx1, 1));
        mx1 = fmaxf(mx1, __shfl_xor_sync(0xffffffffu, mx1, 2));
        const float mn0 = fmaxf(m0, mx0), mn1 = fmaxf(m1, mx1);
        const float corr0 = __expf(m0 - mn0), corr1 = __expf(m1 - mn1);
        m0 = mn0; m1 = mn1;

        float ls0 = 0.0f, ls1 = 0.0f;
#pragma unroll
        for (int f = 0; f < 8; f++) {
            s[f][0] = __expf(s[f][0] - mn0);
            s[f][1] = __expf(s[f][1] - mn0);
            s[f][2] = __expf(s[f][2] - mn1);
            s[f][3] = __expf(s[f][3] - mn1);
            ls0 += s[f][0] + s[f][1];
            ls1 += s[f][2] + s[f][3];
        }
        ls0 += __shfl_xor_sync(0xffffffffu, ls0, 1);
        ls0 += __shfl_xor_sync(0xffffffffu, ls0, 2);
        ls1 += __shfl_xor_sync(0xffffffffu, ls1, 1);
        ls1 += __shfl_xor_sync(0xffffffffu, ls1, 2);
        l0 = l0 * corr0 + ls0;
        l1 = l1 * corr1 + ls1;
#pragma unroll
        for (int f = 0; f < 8; f++) {
            o[f][0] *= corr0; o[f][1] *= corr0;
            o[f][2] *= corr1; o[f][3] *= corr1;
        }

        // ---- pack P into A-fragments (hi/lo) via bit-trick split ----
        uint32_t pah[4][4], pal[4][4];
#pragma unroll
        for (int g = 0; g < 4; g++) {
            split_pair(s[2 * g][0],     s[2 * g][1],     pah[g][0], pal[g][0]);
            split_pair(s[2 * g][2],     s[2 * g][3],     pah[g][1], pal[g][1]);
            split_pair(s[2 * g + 1][0], s[2 * g + 1][1], pah[g][2], pal[g][2]);
            split_pair(s[2 * g + 1][2], s[2 * g + 1][3], pah[g][3], pal[g][3]);
        }

#pragma unroll
        for (int g = 0; g < 4; g++) {
#pragma unroll
            for (int dg = 0; dg < 4; dg++) {
                const uint32_t ba = lmoff + (uint32_t)(g * 16 * AST * 2) + dg * 32;
                uint32_t vh[4], vl[4];
                ldsm4t(vh[0], vh[1], vh[2], vh[3], sVh + ba);
                ldsm4t(vl[0], vl[1], vl[2], vl[3], sVl + ba);
                mma16816(o[2 * dg],     pah[g][0], pah[g][1], pah[g][2], pah[g][3], vh[0], vh[1]);
                mma16816(o[2 * dg + 1], pah[g][0], pah[g][1], pah[g][2], pah[g][3], vh[2], vh[3]);
                mma16816(o[2 * dg],     pah[g][0], pah[g][1], pah[g][2], pah[g][3], vl[0], vl[1]);
                mma16816(o[2 * dg + 1], pah[g][0], pah[g][1], pah[g][2], pah[g][3], vl[2], vl[3]);
                mma16816(o[2 * dg],     pal[g][0], pal[g][1], pal[g][2], pal[g][3], vh[0], vh[1]);
                mma16816(o[2 * dg + 1], pal[g][0], pal[g][1], pal[g][2], pal[g][3], vh[2], vh[3]);
            }
        }
        __syncthreads();
    }

    // ---- epilogue: normalize, gate (sigmoid), bf16 split (bit-trick), write ----
    const float inv0 = 1.0f / l0, inv1 = 1.0f / l1;
    const int row0 = iq0 + w * 16 + gid;
#pragma unroll
    for (int f = 0; f < 8; f++) {
        const int col = h * 64 + 8 * f + qc;
        const float2 gA = *(const float2*)&g_P[(size_t)row0 * 2048 + 1536 + col];
        const float2 gB = *(const float2*)&g_P[(size_t)(row0 + 8) * 2048 + 1536 + col];
        float a0 = o[f][0] * inv0 / (1.0f + __expf(-gA.x));
        float a1 = o[f][1] * inv0 / (1.0f + __expf(-gA.y));
        float a2 = o[f][2] * inv1 / (1.0f + __expf(-gB.x));
        float a3 = o[f][3] * inv1 / (1.0f + __expf(-gB.y));
        uint32_t hA, lA, hB, lB;
        split_pair(a0, a1, hA, lA);
        split_pair(a2, a3, hB, lB);
        *(uint32_t*)&g_ah[(size_t)row0 * 512 + col]       = hA;
        *(uint32_t*)&g_al[(size_t)row0 * 512 + col]       = lA;
        *(uint32_t*)&g_ah[(size_t)(row0 + 8) * 512 + col] = hB;
        *(uint32_t*)&g_al[(size_t)(row0 + 8) * 512 + col] = lB;
    }
}

// ---------------------------------------------------------------------------
extern "C" void kernel_launch(void* const* d_in, const int* in_sizes, int n_in,
                              void* d_out, int out_size)
{
    const float* x     = (const float*)d_in[0];
    const float* Wq    = (const float*)d_in[1];
    const float* Wk    = (const float*)d_in[2];
    const float* Wv    = (const float*)d_in[3];
    const float* Wg    = (const float*)d_in[4];
    const float* bg    = (const float*)d_in[5];
    const float* Wo    = (const float*)d_in[6];
    const float* mem_k = (const float*)d_in[7];
    const float* mem_v = (const float*)d_in[8];
    const float* freqs = (const float*)d_in[9];
    float* out = (float*)d_out;

    cudaFuncSetAttribute(hmma_gemm, cudaFuncAttributeMaxDynamicSharedMemorySize, GEMM_SMEM);

    void *pxh, *pxl, *pWth, *pWtl, *pWoth, *pWotl, *pah, *pal, *pP;
    cudaGetSymbolAddress(&pxh, g_xh);     cudaGetSymbolAddress(&pxl, g_xl);
    cudaGetSymbolAddress(&pWth, g_Wth);   cudaGetSymbolAddress(&pWtl, g_Wtl);
    cudaGetSymbolAddress(&pWoth, g_Woth); cudaGetSymbolAddress(&pWotl, g_Wotl);
    cudaGetSymbolAddress(&pah, g_ah);     cudaGetSymbolAddress(&pal, g_al);
    cudaGetSymbolAddress(&pP, g_P);

    __nv_bfloat16* xh = (__nv_bfloat16*)pxh;     __nv_bfloat16* xl = (__nv_bfloat16*)pxl;
    __nv_bfloat16* Wth = (__nv_bfloat16*)pWth;   __nv_bfloat16* Wtl = (__nv_bfloat16*)pWtl;
    __nv_bfloat16* Woth = (__nv_bfloat16*)pWoth; __nv_bfloat16* Wotl = (__nv_bfloat16*)pWotl;
    __nv_bfloat16* ah = (__nv_bfloat16*)pah;     __nv_bfloat16* al = (__nv_bfloat16*)pal;
    float* P = (float*)pP;

    prologue<<<PRO_CONV_BLKS + PRO_SIN_BLKS + PRO_WT_BLKS, 256>>>(
        x, freqs, Wq, Wk, Wv, Wg, Wo);

    // proj: n-tiles = 2048/64 = 32, m-tiles = 4096/128 = 32
    hmma_gemm<<<dim3(32, 32), 256, GEMM_SMEM>>>(xh, xl, Wth, Wtl, P, 2048, 512, bg, 1536);

    const int tasks = HH * NN + HH * MEMM;
    prep_kernel<<<(tasks + 7) / 8, 256>>>(mem_k, mem_v);

    attn_kernel<<<dim3(32, 8), 256>>>();

    // out: n-tiles = 512/64 = 8, m-tiles = 32
    hmma_gemm<<<dim3(8, 32), 256, GEMM_SMEM>>>(ah, al, Woth, Wotl, out, 512, 512, nullptr, 0);
}

// round 16
// speedup vs baseline: 1.0842x; 1.0293x over previous
#include <cuda_runtime.h>
#include <cuda_bf16.h>
#include <math.h>
#include <cstdint>

#define NN 4096
#define DD 512
#define HH 8
#define DHH 64
#define MEMM 4
#define WINN 512
#define JJ (NN + MEMM)   /* 4100 */
#define JP 4160          /* padded to multiple of 64 */
#define QK_SCALE 10.0f

// ---------------------------------------------------------------------------
// Warp-MMA helpers (arch-neutral PTX: valid under compute_103)
// ---------------------------------------------------------------------------
__device__ __forceinline__ uint32_t smem_to_u32(const void* smem_ptr) {
    uint32_t addr;
    asm("{ .reg .u64 tmp; cvta.to.shared.u64 tmp, %1; cvt.u32.u64 %0, tmp; }"
        : "=r"(addr) : "l"(smem_ptr));
    return addr;
}
__device__ __forceinline__ void ldsm4(uint32_t& r0, uint32_t& r1, uint32_t& r2, uint32_t& r3,
                                      uint32_t a) {
    asm volatile("ldmatrix.sync.aligned.m8n8.x4.shared.b16 {%0,%1,%2,%3}, [%4];"
                 : "=r"(r0), "=r"(r1), "=r"(r2), "=r"(r3) : "r"(a));
}
__device__ __forceinline__ void ldsm4t(uint32_t& r0, uint32_t& r1, uint32_t& r2, uint32_t& r3,
                                       uint32_t a) {
    asm volatile("ldmatrix.sync.aligned.m8n8.x4.trans.shared.b16 {%0,%1,%2,%3}, [%4];"
                 : "=r"(r0), "=r"(r1), "=r"(r2), "=r"(r3) : "r"(a));
}
__device__ __forceinline__ void mma16816(float* d,
                                         uint32_t a0, uint32_t a1, uint32_t a2, uint32_t a3,
                                         uint32_t b0, uint32_t b1) {
    asm volatile("mma.sync.aligned.m16n8k16.row.col.f32.bf16.bf16.f32 "
                 "{%0,%1,%2,%3}, {%4,%5,%6,%7}, {%8,%9}, {%0,%1,%2,%3};"
                 : "+f"(d[0]), "+f"(d[1]), "+f"(d[2]), "+f"(d[3])
                 : "r"(a0), "r"(a1), "r"(a2), "r"(a3), "r"(b0), "r"(b1));
}
__device__ __forceinline__ uint32_t pack_bf16(float a, float b) {
    __nv_bfloat162 h = __floats2bfloat162_rn(a, b);
    return *(uint32_t*)&h;
}
// split a float pair: hi = rn-rounded bf16 pair (packed), lo = residual pair (packed).
// hi floats reconstructed exactly via bit surgery (bf16->fp32 is bits<<16).
__device__ __forceinline__ void split_pair(float a, float b, uint32_t& hi, uint32_t& lo) {
    hi = pack_bf16(a, b);
    const float ha = __uint_as_float(hi << 16);
    const float hb = __uint_as_float(hi & 0xffff0000u);
    lo = pack_bf16(a - ha, b - hb);
}

// ---------------------------------------------------------------------------
// Scratch (device globals)
// ---------------------------------------------------------------------------
__device__ float g_P[NN * 2048];        // fused projection out: [n][Q|K|V|G]
__device__ float g_cos[NN * 64], g_sin[NN * 64];   // rope tables
// bf16 hi/lo splits
__device__ __nv_bfloat16 g_xh[NN * DD],   g_xl[NN * DD];       // x
__device__ __nv_bfloat16 g_Wth[2048 * 512], g_Wtl[2048 * 512]; // [Wq|Wk|Wv|Wg]^T  [n][k]
__device__ __nv_bfloat16 g_Woth[512 * 512], g_Wotl[512 * 512]; // Wo^T [n][k]
__device__ __nv_bfloat16 g_ah[NN * 512],  g_al[NN * 512];      // gated attention out
// attention operands (bf16 hi/lo), zero-padded tails. Q is pre-scaled by QK_SCALE.
__device__ __nv_bfloat16 g_Qh[HH * NN * 64], g_Ql[HH * NN * 64];   // [h][n][d]
__device__ __nv_bfloat16 g_Kh[HH * JP * 64], g_Kl[HH * JP * 64];   // [h][j][d]
__device__ __nv_bfloat16 g_Vh[HH * JP * 64], g_Vl[HH * JP * 64];   // [h][j][d]

// ---------------------------------------------------------------------------
// Merged prologue: conv_split (blocks 0..8191), sincos (8192..9215),
// convert_wt x5 (9216..10495)
// ---------------------------------------------------------------------------
#define PRO_CONV_BLKS  8192
#define PRO_SIN_BLKS   1024
#define PRO_WT_BLKS    1280     /* 5 * 256 */

__global__ void __launch_bounds__(256) prologue(
    const float* __restrict__ x, const float* __restrict__ freqs,
    const float* __restrict__ Wq, const float* __restrict__ Wk,
    const float* __restrict__ Wv, const float* __restrict__ Wg,
    const float* __restrict__ Wo)
{
    const int b = blockIdx.x;
    const int tid = threadIdx.x;
    if (b < PRO_CONV_BLKS) {
        const int i = b * 256 + tid;   // < NN*DD = 2M exactly
        const float v = x[i];
        const __nv_bfloat16 h = __float2bfloat16(v);
        g_xh[i] = h;
        g_xl[i] = __float2bfloat16(v - __bfloat162float(h));
    } else if (b < PRO_CONV_BLKS + PRO_SIN_BLKS) {
        const int i = (b - PRO_CONV_BLKS) * 256 + tid;   // < NN*64 = 256K exactly
        float s, c;
        sincosf(freqs[i], &s, &c);
        g_cos[i] = c;
        g_sin[i] = s;
    } else {
        __shared__ float t[32][33];
        const int bb = b - PRO_CONV_BLKS - PRO_SIN_BLKS;
        const int z = bb >> 8;             // 0..4
        const int tile = bb & 255;
        const float* W = (z == 0) ? Wq : (z == 1) ? Wk : (z == 2) ? Wv : (z == 3) ? Wg : Wo;
        __nv_bfloat16* Dh = (z < 4) ? (g_Wth + (size_t)z * 512 * 512) : g_Woth;
        __nv_bfloat16* Dl = (z < 4) ? (g_Wtl + (size_t)z * 512 * 512) : g_Wotl;
        const int bx = (tile & 15) * 32;   // n
        const int by = (tile >> 4) * 32;   // k
        const int tx = tid & 31, ty = tid >> 5;
#pragma unroll
        for (int i = ty; i < 32; i += 8)
            t[i][tx] = W[(size_t)(by + i) * 512 + bx + tx];
        __syncthreads();
#pragma unroll
        for (int i = ty; i < 32; i += 8) {
            const float v = t[tx][i];
            const __nv_bfloat16 h = __float2bfloat16(v);
            const __nv_bfloat16 l = __float2bfloat16(v - __bfloat162float(h));
            const size_t o = (size_t)(bx + i) * 512 + by + tx;
            Dh[o] = h; Dl[o] = l;
        }
    }
}

// ---------------------------------------------------------------------------
// HMMA split-bf16 GEMM. CTA tile 128(m) x 64(n), warp tile 32x32, 8 warps,
// 3 CTAs/SM. LDG+STS tile fills (unchanged from R10/R12/R15).
// ---------------------------------------------------------------------------
#define SST 72
#define GEMM_SMEM ((2 * 128 + 2 * 64) * SST * 2)   /* 55296 */

__global__ void __launch_bounds__(256, 3) hmma_gemm(
    const __nv_bfloat16* __restrict__ Ah, const __nv_bfloat16* __restrict__ Al,
    const __nv_bfloat16* __restrict__ Bh, const __nv_bfloat16* __restrict__ Bl,
    float* __restrict__ C, int Ntot, int K,
    const float* __restrict__ bias, int bias_off)
{
    extern __shared__ __align__(16) __nv_bfloat16 sm[];
    __nv_bfloat16* sAh = sm;                     // 128 x SST
    __nv_bfloat16* sAl = sm + 128 * SST;         // 128 x SST
    __nv_bfloat16* sBh = sm + 256 * SST;         // 64 x SST
    __nv_bfloat16* sBl = sm + 320 * SST;         // 64 x SST

    const int tid = threadIdx.x;
    const int lane = tid & 31, wid = tid >> 5;
    const int wm = wid & 3, wn = wid >> 2;       // 4 m-warps x 2 n-warps
    const int m0 = blockIdx.y * 128, n0 = blockIdx.x * 64;

    float acc[2][4][4];
#pragma unroll
    for (int i = 0; i < 2; i++)
#pragma unroll
        for (int j = 0; j < 4; j++)
#pragma unroll
            for (int k = 0; k < 4; k++) acc[i][j][k] = 0.0f;

    // loader indices
    const int ar = tid >> 1;               // 0..127
    const int ac = (tid & 1) * 32;         // elems
    const int br = tid >> 2;               // 0..63
    const int bc = (tid & 3) * 16;

    const uint32_t smbase = smem_to_u32(sm);
    const uint32_t afrag = (uint32_t)(((wm * 32 + (lane & 15)) * SST + (lane >> 4) * 8) * 2);
    const uint32_t bfrag = (uint32_t)(((wn * 32 + (lane & 15)) * SST + (lane >> 4) * 8) * 2);
    const uint32_t aAh = smbase + afrag;
    const uint32_t aAl = smbase + 128 * SST * 2 + afrag;
    const uint32_t aBh = smbase + 256 * SST * 2 + bfrag;
    const uint32_t aBl = smbase + 320 * SST * 2 + bfrag;

    for (int kc = 0; kc < K; kc += 64) {
        __syncthreads();
        {
            const size_t ga = (size_t)(m0 + ar) * K + kc + ac;
#pragma unroll
            for (int i = 0; i < 4; i++) {
                *(float4*)&sAh[ar * SST + ac + i * 8] = *(const float4*)&Ah[ga + i * 8];
                *(float4*)&sAl[ar * SST + ac + i * 8] = *(const float4*)&Al[ga + i * 8];
            }
            const size_t gb = (size_t)(n0 + br) * K + kc + bc;
#pragma unroll
            for (int i = 0; i < 2; i++) {
                *(float4*)&sBh[br * SST + bc + i * 8] = *(const float4*)&Bh[gb + i * 8];
                *(float4*)&sBl[br * SST + bc + i * 8] = *(const float4*)&Bl[gb + i * 8];
            }
        }
        __syncthreads();

#pragma unroll
        for (int kk = 0; kk < 4; kk++) {
            const uint32_t ko = kk * 32;
            uint32_t ah[8], al[8], bh[8], bl[8];
            ldsm4(ah[0], ah[1], ah[2], ah[3], aAh + ko);
            ldsm4(ah[4], ah[5], ah[6], ah[7], aAh + ko + 16 * SST * 2);
            ldsm4(al[0], al[1], al[2], al[3], aAl + ko);
            ldsm4(al[4], al[5], al[6], al[7], aAl + ko + 16 * SST * 2);
            ldsm4(bh[0], bh[1], bh[2], bh[3], aBh + ko);
            ldsm4(bh[4], bh[5], bh[6], bh[7], aBh + ko + 16 * SST * 2);
            ldsm4(bl[0], bl[1], bl[2], bl[3], aBl + ko);
            ldsm4(bl[4], bl[5], bl[6], bl[7], aBl + ko + 16 * SST * 2);
#pragma unroll
            for (int bn = 0; bn < 4; bn++) {
                const uint32_t bh0 = bh[(bn >> 1) * 4 + (bn & 1)];
                const uint32_t bh1 = bh[(bn >> 1) * 4 + (bn & 1) + 2];
                const uint32_t bl0 = bl[(bn >> 1) * 4 + (bn & 1)];
                const uint32_t bl1 = bl[(bn >> 1) * 4 + (bn & 1) + 2];
                mma16816(acc[0][bn], ah[0], ah[1], ah[2], ah[3], bh0, bh1);
                mma16816(acc[0][bn], ah[0], ah[1], ah[2], ah[3], bl0, bl1);
                mma16816(acc[0][bn], al[0], al[1], al[2], al[3], bh0, bh1);
                mma16816(acc[1][bn], ah[4], ah[5], ah[6], ah[7], bh0, bh1);
                mma16816(acc[1][bn], ah[4], ah[5], ah[6], ah[7], bl0, bl1);
                mma16816(acc[1][bn], al[4], al[5], al[6], al[7], bh0, bh1);
            }
        }
    }

    const int gid = lane >> 2;
    const int qc = (lane & 3) * 2;
#pragma unroll
    for (int mf = 0; mf < 2; mf++) {
        const int row = m0 + wm * 32 + mf * 16 + gid;
#pragma unroll
        for (int nf = 0; nf < 4; nf++) {
            const int col = n0 + wn * 32 + nf * 8 + qc;
            float2 v0 = make_float2(acc[mf][nf][0], acc[mf][nf][1]);
            float2 v1 = make_float2(acc[mf][nf][2], acc[mf][nf][3]);
            if (bias != nullptr && col >= bias_off) {
                const float b0 = bias[col - bias_off], b1 = bias[col - bias_off + 1];
                v0.x += b0; v0.y += b1;
                v1.x += b0; v1.y += b1;
            }
            *(float2*)&C[(size_t)row * Ntot + col] = v0;
            *(float2*)&C[(size_t)(row + 8) * Ntot + col] = v1;
        }
    }
}

// ---------------------------------------------------------------------------
// prep: per-(h,n) l2norm + RoPE (table-driven), emit bf16 hi/lo Q/K/V.
// Q is pre-scaled by QK_SCALE so attention needs no per-logit scaling.
// ---------------------------------------------------------------------------
__device__ __forceinline__ void split_store(__nv_bfloat16* dh, __nv_bfloat16* dl, float v) {
    __nv_bfloat16 h = __float2bfloat16(v);
    *dh = h;
    *dl = __float2bfloat16(v - __bfloat162float(h));
}

__global__ void __launch_bounds__(256) prep_kernel(
    const float* __restrict__ mem_k, const float* __restrict__ mem_v)
{
    const int warp = (blockIdx.x * blockDim.x + threadIdx.x) >> 5;
    const int lane = threadIdx.x & 31;
    const int total = HH * NN;
    if (warp < total) {
        const int h = warp >> 12;
        const int n = warp & (NN - 1);
        const float c0 = g_cos[n * 64 + lane];
        const float c1 = g_cos[n * 64 + lane + 32];
        const float s0 = g_sin[n * 64 + lane];
        const float s1 = g_sin[n * 64 + lane + 32];
        {
            const float* r = &g_P[n * 2048 + h * 64];
            float t0 = r[lane], t1 = r[lane + 32];
            float ss = t0 * t0 + t1 * t1;
#pragma unroll
            for (int o = 16; o; o >>= 1) ss += __shfl_xor_sync(0xffffffffu, ss, o);
            const float inv = QK_SCALE / fmaxf(sqrtf(ss), 1e-12f);   // scale folded in
            t0 *= inv; t1 *= inv;
            const size_t base = ((size_t)h * NN + n) * 64;
            split_store(&g_Qh[base + lane], &g_Ql[base + lane], t0 * c0 - t1 * s0);
            split_store(&g_Qh[base + lane + 32], &g_Ql[base + lane + 32], t1 * c1 + t0 * s1);
        }
        {
            const float* r = &g_P[n * 2048 + 512 + h * 64];
            float t0 = r[lane], t1 = r[lane + 32];
            float ss = t0 * t0 + t1 * t1;
#pragma unroll
            for (int o = 16; o; o >>= 1) ss += __shfl_xor_sync(0xffffffffu, ss, o);
            const float inv = 1.0f / fmaxf(sqrtf(ss), 1e-12f);
            t0 *= inv; t1 *= inv;
            const size_t base = ((size_t)h * JP + MEMM + n) * 64;
            split_store(&g_Kh[base + lane], &g_Kl[base + lane], t0 * c0 - t1 * s0);
            split_store(&g_Kh[base + lane + 32], &g_Kl[base + lane + 32], t1 * c1 + t0 * s1);
        }
        {
            const float* r = &g_P[n * 2048 + 1024 + h * 64];
            const size_t base = ((size_t)h * JP + MEMM + n) * 64;
            split_store(&g_Vh[base + lane], &g_Vl[base + lane], r[lane]);
            split_store(&g_Vh[base + lane + 32], &g_Vl[base + lane + 32], r[lane + 32]);
        }
    } else if (warp < total + HH * MEMM) {
        const int t = warp - total;
        const int h = t >> 2, m = t & 3;
        const float* r = &mem_k[(h * MEMM + m) * 64];
        float t0 = r[lane], t1 = r[lane + 32];
        float ss = t0 * t0 + t1 * t1;
#pragma unroll
        for (int o = 16; o; o >>= 1) ss += __shfl_xor_sync(0xffffffffu, ss, o);
        const float inv = 1.0f / fmaxf(sqrtf(ss), 1e-12f);
        const size_t kb = ((size_t)h * JP + m) * 64;
        split_store(&g_Kh[kb + lane], &g_Kl[kb + lane], t0 * inv);
        split_store(&g_Kh[kb + lane + 32], &g_Kl[kb + lane + 32], t1 * inv);
        const float* rv = &mem_v[(h * MEMM + m) * 64];
        split_store(&g_Vh[kb + lane], &g_Vl[kb + lane], rv[lane]);
        split_store(&g_Vh[kb + lane + 32], &g_Vl[kb + lane + 32], rv[lane + 32]);
    }
}

// ---------------------------------------------------------------------------
// HMMA banded flash attention, q-tile=128, 8 warps, fused gate epilogue.
// R15 structure + per-warp fully-masked-tile skip (bit-identical fast path).
// ---------------------------------------------------------------------------
#define AST 72

__global__ void __launch_bounds__(256, 2) attn_kernel()
{
    __shared__ __align__(16) __nv_bfloat16 sm4[4][64 * AST];

    const int h = blockIdx.y;
    const int iq0 = blockIdx.x * 128;
    const int tid = threadIdx.x;
    const int lane = tid & 31, w = tid >> 5;
    const int gid = lane >> 2;
    const int qc = (lane & 3) * 2;

    const uint32_t sKh = smem_to_u32(sm4[0]);
    const uint32_t sKl = smem_to_u32(sm4[1]);
    const uint32_t sVh = smem_to_u32(sm4[2]);
    const uint32_t sVl = smem_to_u32(sm4[3]);

    // ---- stage Q (128 rows), load Q frags once ----
    {
        const int r = tid >> 1, half = (tid & 1) * 32;
        const size_t gq = ((size_t)h * NN + iq0 + r) * 64 + half;
        const int so = (r & 63) * AST + half;
        __nv_bfloat16* dsth = (r < 64) ? sm4[0] : sm4[1];
        __nv_bfloat16* dstl = (r < 64) ? sm4[2] : sm4[3];
#pragma unroll
        for (int i = 0; i < 4; i++) {
            *(float4*)&dsth[so + i * 8] = *(const float4*)&g_Qh[gq + i * 8];
            *(float4*)&dstl[so + i * 8] = *(const float4*)&g_Ql[gq + i * 8];
        }
    }
    __syncthreads();
    uint32_t qh[4][4], ql[4][4];
    {
        const int qrow = w * 16 + (lane & 15);
        const uint32_t off = (uint32_t)(((qrow & 63) * AST + (lane >> 4) * 8) * 2);
        const uint32_t bh = ((qrow < 64) ? sKh : sKl) + off;
        const uint32_t bl = ((qrow < 64) ? sVh : sVl) + off;
#pragma unroll
        for (int ks = 0; ks < 4; ks++) {
            ldsm4(qh[ks][0], qh[ks][1], qh[ks][2], qh[ks][3], bh + ks * 32);
            ldsm4(ql[ks][0], ql[ks][1], ql[ks][2], ql[ks][3], bl + ks * 32);
        }
    }
    __syncthreads();

    float o[8][4];
#pragma unroll
    for (int f = 0; f < 8; f++)
#pragma unroll
        for (int k = 0; k < 4; k++) o[f][k] = 0.0f;
    float m0 = -1e9f, m1 = -1e9f, l0 = 0.0f, l1 = 0.0f;

    const int qpos0 = MEMM + iq0 + w * 16 + gid;
    const int qpos1 = qpos0 + 8;
    // warp's q-position range (uniform across lanes)
    const int wql = MEMM + iq0 + w * 16;
    const int wqh = wql + 15;

    int lo = iq0 + MEMM - WINN; if (lo < 0) lo = 0;
    int hi = iq0 + 127 + MEMM + WINN + 1; if (hi > JJ) hi = JJ;

    const uint32_t lmoff = (uint32_t)((((lane & 15)) * AST + (lane >> 4) * 8) * 2);

    for (int j0 = lo & ~63; j0 < hi; j0 += 64) {
        {
            const int r = tid >> 2;
            const int c = (tid & 3) * 16;
            const size_t gb = ((size_t)h * JP + j0 + r) * 64 + c;
            const int so = r * AST + c;
#pragma unroll
            for (int i = 0; i < 2; i++) {
                *(float4*)&sm4[0][so + i * 8] = *(const float4*)&g_Kh[gb + i * 8];
                *(float4*)&sm4[1][so + i * 8] = *(const float4*)&g_Kl[gb + i * 8];
                *(float4*)&sm4[2][so + i * 8] = *(const float4*)&g_Vh[gb + i * 8];
                *(float4*)&sm4[3][so + i * 8] = *(const float4*)&g_Vl[gb + i * 8];
            }
        }
        __syncthreads();

        // per-warp dead-tile skip: tile fully outside this warp's window is a
        // mathematical no-op (all p=0, corr=1) — skip all compute, keep barriers.
        const bool alive = (j0 + 63 >= wql - WINN) && (j0 <= wqh + WINN);
        if (alive) {

        float s[8][4];
#pragma unroll
        for (int f = 0; f < 8; f++)
#pragma unroll
            for (int k = 0; k < 4; k++) s[f][k] = 0.0f;

#pragma unroll
        for (int ks = 0; ks < 4; ks++) {
#pragma unroll
            for (int g = 0; g < 4; g++) {
                const uint32_t ba = lmoff + (uint32_t)(g * 16 * AST * 2) + ks * 32;
                uint32_t kh[4], kl[4];
                ldsm4(kh[0], kh[1], kh[2], kh[3], sKh + ba);
                ldsm4(kl[0], kl[1], kl[2], kl[3], sKl + ba);
                mma16816(s[2 * g],     qh[ks][0], qh[ks][1], qh[ks][2], qh[ks][3], kh[0], kh[2]);
                mma16816(s[2 * g + 1], qh[ks][0], qh[ks][1], qh[ks][2], qh[ks][3], kh[1], kh[3]);
                mma16816(s[2 * g],     qh[ks][0], qh[ks][1], qh[ks][2], qh[ks][3], kl[0], kl[2]);
                mma16816(s[2 * g + 1], qh[ks][0], qh[ks][1], qh[ks][2], qh[ks][3], kl[1], kl[3]);
                mma16816(s[2 * g],     ql[ks][0], ql[ks][1], ql[ks][2], ql[ks][3], kh[0], kh[2]);
                mma16816(s[2 * g + 1], ql[ks][0], ql[ks][1], ql[ks][2], ql[ks][3], kh[1], kh[3]);
            }
        }

        // logits are pre-scaled; only masking remains
        const bool needmask = (MEMM + iq0 + 127 - j0 > WINN) ||
                              (j0 + 63 - (MEMM + iq0) > WINN) ||
                              (j0 + 64 > JJ);
        if (needmask) {
#pragma unroll
            for (int f = 0; f < 8; f++) {
                const int k0 = j0 + 8 * f + qc;
                const int k1 = k0 + 1;
                const bool ok00 = (qpos0 - k0 <= WINN) && (k0 - qpos0 <= WINN) && (k0 < JJ);
                const bool ok01 = (qpos0 - k1 <= WINN) && (k1 - qpos0 <= WINN) && (k1 < JJ);
                const bool ok10 = (qpos1 - k0 <= WINN) && (k0 - qpos1 <= WINN) && (k0 < JJ);
                const bool ok11 = (qpos1 - k1 <= WINN) && (k1 - qpos1 <= WINN) && (k1 < JJ);
                if (!ok00) s[f][0] = -1e30f;
                if (!ok01) s[f][1] = -1e30f;
                if (!ok10) s[f][2] = -1e30f;
                if (!ok11) s[f][3] = -1e30f;
            }
        }

        float mx0 = -1e30f, mx1 = -1e30f;
#pragma unroll
        for (int f = 0; f < 8; f++) {
            mx0 = fmaxf(mx0, fmaxf(s[f][0], s[f][1]));
            mx1 = fmaxf(mx1, fmaxf(s[f][2], s[f][3]));
        }
        mx0 = fmaxf(mx0, __shfl_xor_sync(0xffffffffu, mx0, 1));
        mx0 = fmaxf(mx0, __shfl_xor_sync(0xffffffffu, mx0, 2));
        mx1 = fmaxf(mx1, __shfl_xor_sync(0xffffffffu, mx1, 1));
        mx1 = fmaxf(mx1, __shfl_xor_sync(0xffffffffu, mx1, 2));
        const float mn0 = fmaxf(m0, mx0), mn1 = fmaxf(m1, mx1);
        const float corr0 = __expf(m0 - mn0), corr1 = __expf(m1 - mn1);
        m0 = mn0; m1 = mn1;

        float ls0 = 0.0f, ls1 = 0.0f;
#pragma unroll
        for (int f = 0; f < 8; f++) {
            s[f][0] = __expf(s[f][0] - mn0);
            s[f][1] = __expf(s[f][1] - mn0);
            s[f][2] = __expf(s[f][2] - mn1);
            s[f][3] = __expf(s[f][3] - mn1);
            ls0 += s[f][0] + s[f][1];
            ls1 += s[f][2] + s[f][3];
        }
        ls0 += __shfl_xor_sync(0xffffffffu, ls0, 1);
        ls0 += __shfl_xor_sync(0xffffffffu, ls0, 2);
        ls1 += __shfl_xor_sync(0xffffffffu, ls1, 1);
        ls1 += __shfl_xor_sync(0xffffffffu, ls1, 2);
        l0 = l0 * corr0 + ls0;
        l1 = l1 * corr1 + ls1;
#pragma unroll
        for (int f = 0; f < 8; f++) {
            o[f][0] *= corr0; o[f][1] *= corr0;
            o[f][2] *= corr1; o[f][3] *= corr1;
        }

        // ---- pack P into A-fragments (hi/lo) via bit-trick split ----
        uint32_t pah[4][4], pal[4][4];
#pragma unroll
        for (int g = 0; g < 4; g++) {
            split_pair(s[2 * g][0],     s[2 * g][1],     pah[g][0], pal[g][0]);
            split_pair(s[2 * g][2],     s[2 * g][3],     pah[g][1], pal[g][1]);
            split_pair(s[2 * g + 1][0], s[2 * g + 1][1], pah[g][2], pal[g][2]);
            split_pair(s[2 * g + 1][2], s[2 * g + 1][3], pah[g][3], pal[g][3]);
        }

#pragma unroll
        for (int g = 0; g < 4; g++) {
#pragma unroll
            for (int dg = 0; dg < 4; dg++) {
                const uint32_t ba = lmoff + (uint32_t)(g * 16 * AST * 2) + dg * 32;
                uint32_t vh[4], vl[4];
                ldsm4t(vh[0], vh[1], vh[2], vh[3], sVh + ba);
                ldsm4t(vl[0], vl[1], vl[2], vl[3], sVl + ba);
                mma16816(o[2 * dg],     pah[g][0], pah[g][1], pah[g][2], pah[g][3], vh[0], vh[1]);
                mma16816(o[2 * dg + 1], pah[g][0], pah[g][1], pah[g][2], pah[g][3], vh[2], vh[3]);
                mma16816(o[2 * dg],     pah[g][0], pah[g][1], pah[g][2], pah[g][3], vl[0], vl[1]);
                mma16816(o[2 * dg + 1], pah[g][0], pah[g][1], pah[g][2], pah[g][3], vl[2], vl[3]);
                mma16816(o[2 * dg],     pal[g][0], pal[g][1], pal[g][2], pal[g][3], vh[0], vh[1]);
                mma16816(o[2 * dg + 1], pal[g][0], pal[g][1], pal[g][2], pal[g][3], vh[2], vh[3]);
            }
        }

        } // alive
        __syncthreads();
    }

    // ---- epilogue: normalize, gate (sigmoid), bf16 split (bit-trick), write ----
    const float inv0 = 1.0f / l0, inv1 = 1.0f / l1;
    const int row0 = iq0 + w * 16 + gid;
#pragma unroll
    for (int f = 0; f < 8; f++) {
        const int col = h * 64 + 8 * f + qc;
        const float2 gA = *(const float2*)&g_P[(size_t)row0 * 2048 + 1536 + col];
        const float2 gB = *(const float2*)&g_P[(size_t)(row0 + 8) * 2048 + 1536 + col];
        float a0 = o[f][0] * inv0 / (1.0f + __expf(-gA.x));
        float a1 = o[f][1] * inv0 / (1.0f + __expf(-gA.y));
        float a2 = o[f][2] * inv1 / (1.0f + __expf(-gB.x));
        float a3 = o[f][3] * inv1 / (1.0f + __expf(-gB.y));
        uint32_t hA, lA, hB, lB;
        split_pair(a0, a1, hA, lA);
        split_pair(a2, a3, hB, lB);
        *(uint32_t*)&g_ah[(size_t)row0 * 512 + col]       = hA;
        *(uint32_t*)&g_al[(size_t)row0 * 512 + col]       = lA;
        *(uint32_t*)&g_ah[(size_t)(row0 + 8) * 512 + col] = hB;
        *(uint32_t*)&g_al[(size_t)(row0 + 8) * 512 + col] = lB;
    }
}

// ---------------------------------------------------------------------------
extern "C" void kernel_launch(void* const* d_in, const int* in_sizes, int n_in,
                              void* d_out, int out_size)
{
    const float* x     = (const float*)d_in[0];
    const float* Wq    = (const float*)d_in[1];
    const float* Wk    = (const float*)d_in[2];
    const float* Wv    = (const float*)d_in[3];
    const float* Wg    = (const float*)d_in[4];
    const float* bg    = (const float*)d_in[5];
    const float* Wo    = (const float*)d_in[6];
    const float* mem_k = (const float*)d_in[7];
    const float* mem_v = (const float*)d_in[8];
    const float* freqs = (const float*)d_in[9];
    float* out = (float*)d_out;

    cudaFuncSetAttribute(hmma_gemm, cudaFuncAttributeMaxDynamicSharedMemorySize, GEMM_SMEM);

    void *pxh, *pxl, *pWth, *pWtl, *pWoth, *pWotl, *pah, *pal, *pP;
    cudaGetSymbolAddress(&pxh, g_xh);     cudaGetSymbolAddress(&pxl, g_xl);
    cudaGetSymbolAddress(&pWth, g_Wth);   cudaGetSymbolAddress(&pWtl, g_Wtl);
    cudaGetSymbolAddress(&pWoth, g_Woth); cudaGetSymbolAddress(&pWotl, g_Wotl);
    cudaGetSymbolAddress(&pah, g_ah);     cudaGetSymbolAddress(&pal, g_al);
    cudaGetSymbolAddress(&pP, g_P);

    __nv_bfloat16* xh = (__nv_bfloat16*)pxh;     __nv_bfloat16* xl = (__nv_bfloat16*)pxl;
    __nv_bfloat16* Wth = (__nv_bfloat16*)pWth;   __nv_bfloat16* Wtl = (__nv_bfloat16*)pWtl;
    __nv_bfloat16* Woth = (__nv_bfloat16*)pWoth; __nv_bfloat16* Wotl = (__nv_bfloat16*)pWotl;
    __nv_bfloat16* ah = (__nv_bfloat16*)pah;     __nv_bfloat16* al = (__nv_bfloat16*)pal;
    float* P = (float*)pP;

    prologue<<<PRO_CONV_BLKS + PRO_SIN_BLKS + PRO_WT_BLKS, 256>>>(
        x, freqs, Wq, Wk, Wv, Wg, Wo);

    // proj: n-tiles = 2048/64 = 32, m-tiles = 4096/128 = 32
    hmma_gemm<<<dim3(32, 32), 256, GEMM_SMEM>>>(xh, xl, Wth, Wtl, P, 2048, 512, bg, 1536);

    const int tasks = HH * NN + HH * MEMM;
    prep_kernel<<<(tasks + 7) / 8, 256>>>(mem_k, mem_v);

    attn_kernel<<<dim3(32, 8), 256>>>();

    // out: n-tiles = 512/64 = 8, m-tiles = 32
    hmma_gemm<<<dim3(8, 32), 256, GEMM_SMEM>>>(ah, al, Woth, Wotl, out, 512, 512, nullptr, 0);
}